// round 4
// baseline (speedup 1.0000x reference)
#include <cuda_runtime.h>
#include <math.h>
#include <stdint.h>

#define B_ 8
#define T_ 2048
#define V_ 1024
#define C_ 128
#define NB2 64   // 2*NB
#define S_ 64    // chunk size
#define NCH 32   // T_/S_

// ---------------- device scratch ----------------
__device__ float g_wqkv[V_ * 3 * C_];       // (V, 384)
__device__ float g_qkv[B_ * T_ * 3 * C_];   // (B*T, 384)
__device__ float g_r[B_ * T_ * C_];         // retrieved (B*T, 128)
__device__ float g_r2[B_ * T_ * NB2];       // retrieved @ oc  (B*T, 64)
__device__ float g_G[B_ * NCH * C_ * C_];   // per-chunk outer-product sums
__device__ float g_M[B_ * NCH * C_ * C_];   // chunk-boundary states

__device__ __forceinline__ float sigmoidf_(float x) { return 1.0f / (1.0f + expf(-x)); }

__device__ __forceinline__ uint32_t f2tf32(float x) {
    uint32_t r;
    asm("cvt.rna.tf32.f32 %0, %1;" : "=r"(r) : "f"(x));
    return r;
}

__device__ __forceinline__ void mma_tf32(float* c, const uint32_t* a, const uint32_t* b) {
    asm volatile(
        "mma.sync.aligned.m16n8k8.row.col.f32.tf32.tf32.f32 "
        "{%0,%1,%2,%3}, {%4,%5,%6,%7}, {%8,%9}, {%0,%1,%2,%3};"
        : "+f"(c[0]), "+f"(c[1]), "+f"(c[2]), "+f"(c[3])
        : "r"(a[0]), "r"(a[1]), "r"(a[2]), "r"(a[3]), "r"(b[0]), "r"(b[1]));
}

// ---------------- 1) weights: basis @ coeffs^T (+ softmax over V), q/k/v only ----------------
__global__ void weights_kernel(const float* __restrict__ basis,
                               const float* __restrict__ qc,
                               const float* __restrict__ kc,
                               const float* __restrict__ vc) {
    const int c = blockIdx.x;
    const int w = blockIdx.y;   // 0=q 1=k 2=v
    const int v = threadIdx.x;

    const float* coef = (w == 0 ? qc : (w == 1 ? kc : vc)) + c * NB2;
    __shared__ float scoef[NB2];
    __shared__ float red[32];
    __shared__ float sval;
    if (v < NB2) scoef[v] = coef[v];
    __syncthreads();

    float s = 0.f;
    const float4* brow = (const float4*)(basis + (size_t)v * NB2);
    #pragma unroll
    for (int jj = 0; jj < NB2 / 4; jj++) {
        float4 bv = brow[jj];
        s = fmaf(bv.x, scoef[4 * jj + 0], s);
        s = fmaf(bv.y, scoef[4 * jj + 1], s);
        s = fmaf(bv.z, scoef[4 * jj + 2], s);
        s = fmaf(bv.w, scoef[4 * jj + 3], s);
    }

    float m = s;
    #pragma unroll
    for (int o = 16; o; o >>= 1) m = fmaxf(m, __shfl_xor_sync(0xffffffffu, m, o));
    if ((v & 31) == 0) red[v >> 5] = m;
    __syncthreads();
    if (v < 32) {
        float t = red[v];
        #pragma unroll
        for (int o = 16; o; o >>= 1) t = fmaxf(t, __shfl_xor_sync(0xffffffffu, t, o));
        if (v == 0) sval = t;
    }
    __syncthreads();
    float e = expf(s - sval);

    float su = e;
    #pragma unroll
    for (int o = 16; o; o >>= 1) su += __shfl_xor_sync(0xffffffffu, su, o);
    if ((v & 31) == 0) red[v >> 5] = su;
    __syncthreads();
    if (v < 32) {
        float t = red[v];
        #pragma unroll
        for (int o = 16; o; o >>= 1) t += __shfl_xor_sync(0xffffffffu, t, o);
        if (v == 0) sval = t;
    }
    __syncthreads();

    g_wqkv[(size_t)v * (3 * C_) + w * C_ + c] = e / sval;
}

// ---------------- 2) QKV GEMM via tensor cores (tf32 x3), v2 ----------------
// g_qkv (16384x384) = x (16384x1024) @ g_wqkv (1024x384)
// BM=128, BN=128, BK=8, 256 threads (8 warps), warp tile 64x32.
// fp32 -> tf32 hi/lo conversion ONCE at smem store; inner loop is LDS+MMA only.
#define QP 132  // smem pitch (bank-conflict-free: shift 4 banks per row)
__global__ __launch_bounds__(256) void qkv_mma_kernel(const float* __restrict__ A) {
    constexpr int K = V_;       // 1024
    constexpr int N = 3 * C_;   // 384
    __shared__ uint32_t Ah[2][8][QP], Al[2][8][QP];
    __shared__ uint32_t Bh[2][8][QP], Bl[2][8][QP];

    const int tid = threadIdx.x;
    const int bm = blockIdx.y * 128;
    const int bn = blockIdx.x * 128;
    const int warp = tid >> 5, lane = tid & 31;
    const int g = lane >> 2, tg = lane & 3;
    const int wm = (warp >> 2) * 64;    // 0 or 64
    const int wn = (warp & 3) * 32;     // 0,32,64,96

    const int am = tid >> 1, ak = (tid & 1) * 4;        // A: 128 rows x 8 k
    const int bk = tid >> 5, bn4 = (tid & 31) * 4;      // B: 8 k x 128 n

    float acc[4][4][4] = {};
    float4 ra, rb;

    // prologue: tile k0=0
    ra = *(const float4*)(A + (size_t)(bm + am) * K + ak);
    rb = *(const float4*)(g_wqkv + (size_t)bk * N + bn + bn4);
    {
        float av[4] = {ra.x, ra.y, ra.z, ra.w};
        #pragma unroll
        for (int j2 = 0; j2 < 4; j2++) {
            uint32_t h = f2tf32(av[j2]);
            Ah[0][ak + j2][am] = h;
            Al[0][ak + j2][am] = f2tf32(av[j2] - __uint_as_float(h));
        }
        float bv[4] = {rb.x, rb.y, rb.z, rb.w};
        uint32_t h4[4], l4[4];
        #pragma unroll
        for (int j2 = 0; j2 < 4; j2++) {
            h4[j2] = f2tf32(bv[j2]);
            l4[j2] = f2tf32(bv[j2] - __uint_as_float(h4[j2]));
        }
        *(uint4*)&Bh[0][bk][bn4] = make_uint4(h4[0], h4[1], h4[2], h4[3]);
        *(uint4*)&Bl[0][bk][bn4] = make_uint4(l4[0], l4[1], l4[2], l4[3]);
    }
    __syncthreads();

    int buf = 0;
    for (int k0 = 0; k0 < K; k0 += 8) {
        const bool has_next = (k0 + 8 < K);
        if (has_next) {
            ra = *(const float4*)(A + (size_t)(bm + am) * K + k0 + 8 + ak);
            rb = *(const float4*)(g_wqkv + (size_t)(k0 + 8 + bk) * N + bn + bn4);
        }

        // B fragments
        uint32_t bh[4][2], bl[4][2];
        #pragma unroll
        for (int ni = 0; ni < 4; ni++) {
            const int nc = wn + ni * 8 + g;
            bh[ni][0] = Bh[buf][tg][nc];
            bh[ni][1] = Bh[buf][tg + 4][nc];
            bl[ni][0] = Bl[buf][tg][nc];
            bl[ni][1] = Bl[buf][tg + 4][nc];
        }
        #pragma unroll
        for (int mi = 0; mi < 4; mi++) {
            const int mr = wm + mi * 16 + g;
            uint32_t ah[4], al[4];
            ah[0] = Ah[buf][tg][mr];     ah[1] = Ah[buf][tg][mr + 8];
            ah[2] = Ah[buf][tg + 4][mr]; ah[3] = Ah[buf][tg + 4][mr + 8];
            al[0] = Al[buf][tg][mr];     al[1] = Al[buf][tg][mr + 8];
            al[2] = Al[buf][tg + 4][mr]; al[3] = Al[buf][tg + 4][mr + 8];
            #pragma unroll
            for (int ni = 0; ni < 4; ni++) {
                mma_tf32(acc[mi][ni], al, bh[ni]);
                mma_tf32(acc[mi][ni], ah, bl[ni]);
                mma_tf32(acc[mi][ni], ah, bh[ni]);
            }
        }

        if (has_next) {
            float av[4] = {ra.x, ra.y, ra.z, ra.w};
            #pragma unroll
            for (int j2 = 0; j2 < 4; j2++) {
                uint32_t h = f2tf32(av[j2]);
                Ah[buf ^ 1][ak + j2][am] = h;
                Al[buf ^ 1][ak + j2][am] = f2tf32(av[j2] - __uint_as_float(h));
            }
            float bv[4] = {rb.x, rb.y, rb.z, rb.w};
            uint32_t h4[4], l4[4];
            #pragma unroll
            for (int j2 = 0; j2 < 4; j2++) {
                h4[j2] = f2tf32(bv[j2]);
                l4[j2] = f2tf32(bv[j2] - __uint_as_float(h4[j2]));
            }
            *(uint4*)&Bh[buf ^ 1][bk][bn4] = make_uint4(h4[0], h4[1], h4[2], h4[3]);
            *(uint4*)&Bl[buf ^ 1][bk][bn4] = make_uint4(l4[0], l4[1], l4[2], l4[3]);
        }
        __syncthreads();
        buf ^= 1;
    }

    // epilogue
    #pragma unroll
    for (int mi = 0; mi < 4; mi++) {
        const int r0 = bm + wm + mi * 16 + g;
        #pragma unroll
        for (int ni = 0; ni < 4; ni++) {
            const int col = bn + wn + ni * 8 + tg * 2;
            *(float2*)(g_qkv + (size_t)r0 * N + col)       = make_float2(acc[mi][ni][0], acc[mi][ni][1]);
            *(float2*)(g_qkv + (size_t)(r0 + 8) * N + col) = make_float2(acc[mi][ni][2], acc[mi][ni][3]);
        }
    }
}

// ---------------- 3a) per-chunk outer-product sums ----------------
__global__ __launch_bounds__(256) void chunk_g_kernel(const float* __restrict__ decay_ptr) {
    const int cg = blockIdx.x;
    const int j  = blockIdx.y;
    const int b  = blockIdx.z;
    const float dec = sigmoidf_(decay_ptr[0]);
    const float l2d = log2f(dec);

    __shared__ float Ks[32][128];
    __shared__ float Vs[32][32];

    const int tid = threadIdx.x;
    const int trow = tid >> 3;
    const int tcol = tid & 7;
    const int r  = tid >> 3;
    const int q8 = tid & 7;

    float acc[4][4] = {};
    const float* base = g_qkv + ((size_t)b * T_ + (size_t)j * S_) * (3 * C_);

    #pragma unroll
    for (int i0 = 0; i0 < S_; i0 += 32) {
        const float sc = exp2f((float)(S_ - 1 - (i0 + r)) * l2d);
        const float* krow = base + (size_t)(i0 + r) * (3 * C_) + C_;
        #pragma unroll
        for (int u = 0; u < 4; u++) {
            float4 kv = *(const float4*)(krow + (q8 + u * 8) * 4);
            Ks[r][(q8 + u * 8) * 4 + 0] = kv.x * sc;
            Ks[r][(q8 + u * 8) * 4 + 1] = kv.y * sc;
            Ks[r][(q8 + u * 8) * 4 + 2] = kv.z * sc;
            Ks[r][(q8 + u * 8) * 4 + 3] = kv.w * sc;
        }
        *(float4*)&Vs[r][q8 * 4] =
            *(const float4*)(base + (size_t)(i0 + r) * (3 * C_) + 2 * C_ + cg * 32 + q8 * 4);
        __syncthreads();
        #pragma unroll
        for (int ii = 0; ii < 32; ii++) {
            float4 a4 = *(const float4*)&Ks[ii][trow * 4];
            float4 b4 = *(const float4*)&Vs[ii][tcol * 4];
            float ar[4] = {a4.x, a4.y, a4.z, a4.w};
            float br[4] = {b4.x, b4.y, b4.z, b4.w};
            #pragma unroll
            for (int m = 0; m < 4; m++)
                #pragma unroll
                for (int n = 0; n < 4; n++)
                    acc[m][n] = fmaf(ar[m], br[n], acc[m][n]);
        }
        __syncthreads();
    }

    float* gout = g_G + ((size_t)(b * NCH + j) * C_ * C_) + cg * 32;
    #pragma unroll
    for (int m = 0; m < 4; m++)
        *(float4*)(gout + (size_t)(trow * 4 + m) * C_ + tcol * 4) =
            make_float4(acc[m][0], acc[m][1], acc[m][2], acc[m][3]);
}

// ---------------- 3b) scan with batched prefetch ----------------
__global__ void scan_kernel(const float* __restrict__ decay_ptr) {
    const int idx = blockIdx.x * blockDim.x + threadIdx.x;
    const int b = idx >> 12;
    const int e4 = idx & 4095;
    const float dec = sigmoidf_(decay_ptr[0]);
    const float dS = exp2f((float)S_ * log2f(dec));

    const float4* G = (const float4*)(g_G + (size_t)b * NCH * C_ * C_) + e4;
    float4* M = (float4*)(g_M + (size_t)b * NCH * C_ * C_) + e4;

    float4 m = make_float4(0.f, 0.f, 0.f, 0.f);
    #pragma unroll
    for (int jb = 0; jb < NCH; jb += 8) {
        float4 buf[8];
        #pragma unroll
        for (int u = 0; u < 8; u++) buf[u] = G[(size_t)(jb + u) * 4096];
        #pragma unroll
        for (int u = 0; u < 8; u++) {
            M[(size_t)(jb + u) * 4096] = m;
            m.x = fmaf(dS, m.x, buf[u].x);
            m.y = fmaf(dS, m.y, buf[u].y);
            m.z = fmaf(dS, m.z, buf[u].z);
            m.w = fmaf(dS, m.w, buf[u].w);
        }
    }
}

// ---------------- 3c) retrieval per chunk ----------------
__global__ __launch_bounds__(256) void retr_kernel(const float* __restrict__ decay_ptr) {
    const int j = blockIdx.x;
    const int b = blockIdx.y;
    const float dec = sigmoidf_(decay_ptr[0]);
    const float l2d = log2f(dec);

    __shared__ float Qs[32][64];
    __shared__ float Ks2[32][64];
    __shared__ float As[64][64];
    __shared__ float Vs[32][128];

    const int tid = threadIdx.x;
    const float* base = g_qkv + ((size_t)b * T_ + (size_t)j * S_) * (3 * C_);

    {
        const int ti = tid >> 4;
        const int ts = tid & 15;
        const int li = tid >> 2;
        const int lp = tid & 3;

        float acc[4][4] = {};
        for (int c0 = 0; c0 < C_; c0 += 32) {
            #pragma unroll
            for (int u = 0; u < 2; u++) {
                int c = lp * 8 + u * 4;
                float4 qv = *(const float4*)(base + (size_t)li * (3 * C_) + c0 + c);
                Qs[c + 0][li] = qv.x; Qs[c + 1][li] = qv.y;
                Qs[c + 2][li] = qv.z; Qs[c + 3][li] = qv.w;
                float4 kv = *(const float4*)(base + (size_t)li * (3 * C_) + C_ + c0 + c);
                Ks2[c + 0][li] = kv.x; Ks2[c + 1][li] = kv.y;
                Ks2[c + 2][li] = kv.z; Ks2[c + 3][li] = kv.w;
            }
            __syncthreads();
            #pragma unroll
            for (int cc = 0; cc < 32; cc++) {
                float4 a4 = *(const float4*)&Qs[cc][ti * 4];
                float4 b4 = *(const float4*)&Ks2[cc][ts * 4];
                float ar[4] = {a4.x, a4.y, a4.z, a4.w};
                float br[4] = {b4.x, b4.y, b4.z, b4.w};
                #pragma unroll
                for (int m = 0; m < 4; m++)
                    #pragma unroll
                    for (int n = 0; n < 4; n++)
                        acc[m][n] = fmaf(ar[m], br[n], acc[m][n]);
            }
            __syncthreads();
        }
        #pragma unroll
        for (int m = 0; m < 4; m++) {
            const int i = ti * 4 + m;
            #pragma unroll
            for (int n = 0; n < 4; n++) {
                const int s = ts * 4 + n;
                float v = 0.f;
                if (s < i) v = acc[m][n] * exp2f((float)(i - 1 - s) * l2d);
                As[s][i] = v;
            }
        }
    }
    __syncthreads();

    const int ti2 = tid >> 4;
    const int td  = tid & 15;
    const int lr  = tid >> 3;
    const int lq  = tid & 7;

    float accA[4][8] = {};
    float accM[4][8] = {};

    for (int s0 = 0; s0 < S_; s0 += 32) {
        #pragma unroll
        for (int u = 0; u < 4; u++) {
            int c4 = lq + u * 8;
            *(float4*)&Vs[lr][c4 * 4] =
                *(const float4*)(base + (size_t)(s0 + lr) * (3 * C_) + 2 * C_ + c4 * 4);
        }
        __syncthreads();
        #pragma unroll
        for (int ss = 0; ss < 32; ss++) {
            float4 a4 = *(const float4*)&As[s0 + ss][ti2 * 4];
            float4 b0 = *(const float4*)&Vs[ss][td * 8];
            float4 b1 = *(const float4*)&Vs[ss][td * 8 + 4];
            float ar[4] = {a4.x, a4.y, a4.z, a4.w};
            float br[8] = {b0.x, b0.y, b0.z, b0.w, b1.x, b1.y, b1.z, b1.w};
            #pragma unroll
            for (int m = 0; m < 4; m++)
                #pragma unroll
                for (int n = 0; n < 8; n++)
                    accA[m][n] = fmaf(ar[m], br[n], accA[m][n]);
        }
        __syncthreads();
    }

    const float* Mbase = g_M + (size_t)(b * NCH + j) * C_ * C_;
    {
        const int li = tid >> 2;
        const int lp = tid & 3;
        for (int c0 = 0; c0 < C_; c0 += 32) {
            #pragma unroll
            for (int u = 0; u < 2; u++) {
                int c = lp * 8 + u * 4;
                float4 qv = *(const float4*)(base + (size_t)li * (3 * C_) + c0 + c);
                Qs[c + 0][li] = qv.x; Qs[c + 1][li] = qv.y;
                Qs[c + 2][li] = qv.z; Qs[c + 3][li] = qv.w;
            }
            #pragma unroll
            for (int u = 0; u < 4; u++) {
                int c4 = lq + u * 8;
                *(float4*)&Vs[lr][c4 * 4] =
                    *(const float4*)(Mbase + (size_t)(c0 + lr) * C_ + c4 * 4);
            }
            __syncthreads();
            #pragma unroll
            for (int cc = 0; cc < 32; cc++) {
                float4 a4 = *(const float4*)&Qs[cc][ti2 * 4];
                float4 b0 = *(const float4*)&Vs[cc][td * 8];
                float4 b1 = *(const float4*)&Vs[cc][td * 8 + 4];
                float ar[4] = {a4.x, a4.y, a4.z, a4.w};
                float br[8] = {b0.x, b0.y, b0.z, b0.w, b1.x, b1.y, b1.z, b1.w};
                #pragma unroll
                for (int m = 0; m < 4; m++)
                    #pragma unroll
                    for (int n = 0; n < 8; n++)
                        accM[m][n] = fmaf(ar[m], br[n], accM[m][n]);
            }
            __syncthreads();
        }
    }

    float* rout = g_r + ((size_t)b * T_ + (size_t)j * S_) * C_;
    #pragma unroll
    for (int m = 0; m < 4; m++) {
        const int i = ti2 * 4 + m;
        const float di = exp2f((float)i * l2d);
        float o[8];
        #pragma unroll
        for (int n = 0; n < 8; n++) o[n] = fmaf(di, accM[m][n], accA[m][n]);
        *(float4*)(rout + (size_t)i * C_ + td * 8)     = make_float4(o[0], o[1], o[2], o[3]);
        *(float4*)(rout + (size_t)i * C_ + td * 8 + 4) = make_float4(o[4], o[5], o[6], o[7]);
    }
}

// ---------------- 4a) r2 = g_r (16384x128) @ oc (128x64) ----------------
__global__ __launch_bounds__(256) void oc_gemm_kernel(const float* __restrict__ oc) {
    constexpr int BK = 16;
    __shared__ float As[BK][C_];
    __shared__ float Bs[BK][NB2];

    const int tid = threadIdx.x;
    const int bm = blockIdx.x * 128;
    const int trow = tid >> 4;
    const int tcol = tid & 15;

    float acc[8][4] = {};

    for (int k0 = 0; k0 < C_; k0 += BK) {
        #pragma unroll
        for (int t = 0; t < 2; t++) {
            int idx = tid + t * 256;
            int m = idx >> 2, k4 = (idx & 3) * 4;
            float4 a4 = *(const float4*)(g_r + (size_t)(bm + m) * C_ + k0 + k4);
            As[k4 + 0][m] = a4.x; As[k4 + 1][m] = a4.y;
            As[k4 + 2][m] = a4.z; As[k4 + 3][m] = a4.w;
        }
        {
            int k = tid >> 4, n4 = (tid & 15) * 4;
            *(float4*)&Bs[k][n4] = *(const float4*)(oc + (size_t)(k0 + k) * NB2 + n4);
        }
        __syncthreads();
        #pragma unroll
        for (int kk = 0; kk < BK; kk++) {
            float ar[8], br[4];
            *(float4*)&ar[0] = *(const float4*)&As[kk][trow * 8];
            *(float4*)&ar[4] = *(const float4*)&As[kk][trow * 8 + 4];
            *(float4*)&br[0] = *(const float4*)&Bs[kk][tcol * 4];
            #pragma unroll
            for (int i = 0; i < 8; i++)
                #pragma unroll
                for (int jn = 0; jn < 4; jn++)
                    acc[i][jn] = fmaf(ar[i], br[jn], acc[i][jn]);
        }
        __syncthreads();
    }
    #pragma unroll
    for (int i = 0; i < 8; i++)
        *(float4*)(g_r2 + (size_t)(bm + trow * 8 + i) * NB2 + tcol * 4) =
            make_float4(acc[i][0], acc[i][1], acc[i][2], acc[i][3]);
}

// ---------------- 4b) out = g_r2 (16384x64) @ basis^T (64x1024) * scale, tf32 MMA ----------------
__global__ __launch_bounds__(256) void out2_mma_kernel(float* __restrict__ Cout,
                                                       const float* __restrict__ basis,
                                                       const float* __restrict__ scale_ptr) {
    constexpr int K = NB2;   // 64
    constexpr int N = V_;    // 1024
    __shared__ uint32_t Ah[2][8][QP], Al[2][8][QP];
    __shared__ uint32_t Bh[2][8][QP], Bl[2][8][QP];

    const int tid = threadIdx.x;
    const int bm = blockIdx.y * 128;
    const int bn = blockIdx.x * 128;
    const int warp = tid >> 5, lane = tid & 31;
    const int g = lane >> 2, tg = lane & 3;
    const int wm = (warp >> 2) * 64;
    const int wn = (warp & 3) * 32;

    const int am = tid >> 1, ak = (tid & 1) * 4;   // both operands: 128 rows x 8 k

    float acc[4][4][4] = {};
    float4 ra, rb;

    ra = *(const float4*)(g_r2 + (size_t)(bm + am) * K + ak);
    rb = *(const float4*)(basis + (size_t)(bn + am) * K + ak);
    {
        float av[4] = {ra.x, ra.y, ra.z, ra.w};
        float bv[4] = {rb.x, rb.y, rb.z, rb.w};
        #pragma unroll
        for (int j2 = 0; j2 < 4; j2++) {
            uint32_t h = f2tf32(av[j2]);
            Ah[0][ak + j2][am] = h;
            Al[0][ak + j2][am] = f2tf32(av[j2] - __uint_as_float(h));
            uint32_t hb = f2tf32(bv[j2]);
            Bh[0][ak + j2][am] = hb;
            Bl[0][ak + j2][am] = f2tf32(bv[j2] - __uint_as_float(hb));
        }
    }
    __syncthreads();

    int buf = 0;
    for (int k0 = 0; k0 < K; k0 += 8) {
        const bool has_next = (k0 + 8 < K);
        if (has_next) {
            ra = *(const float4*)(g_r2 + (size_t)(bm + am) * K + k0 + 8 + ak);
            rb = *(const float4*)(basis + (size_t)(bn + am) * K + k0 + 8 + ak);
        }

        uint32_t bh[4][2], bl[4][2];
        #pragma unroll
        for (int ni = 0; ni < 4; ni++) {
            const int nc = wn + ni * 8 + g;
            bh[ni][0] = Bh[buf][tg][nc];
            bh[ni][1] = Bh[buf][tg + 4][nc];
            bl[ni][0] = Bl[buf][tg][nc];
            bl[ni][1] = Bl[buf][tg + 4][nc];
        }
        #pragma unroll
        for (int mi = 0; mi < 4; mi++) {
            const int mr = wm + mi * 16 + g;
            uint32_t ah[4], al[4];
            ah[0] = Ah[buf][tg][mr];     ah[1] = Ah[buf][tg][mr + 8];
            ah[2] = Ah[buf][tg + 4][mr]; ah[3] = Ah[buf][tg + 4][mr + 8];
            al[0] = Al[buf][tg][mr];     al[1] = Al[buf][tg][mr + 8];
            al[2] = Al[buf][tg + 4][mr]; al[3] = Al[buf][tg + 4][mr + 8];
            #pragma unroll
            for (int ni = 0; ni < 4; ni++) {
                mma_tf32(acc[mi][ni], al, bh[ni]);
                mma_tf32(acc[mi][ni], ah, bl[ni]);
                mma_tf32(acc[mi][ni], ah, bh[ni]);
            }
        }

        if (has_next) {
            float av[4] = {ra.x, ra.y, ra.z, ra.w};
            float bv[4] = {rb.x, rb.y, rb.z, rb.w};
            #pragma unroll
            for (int j2 = 0; j2 < 4; j2++) {
                uint32_t h = f2tf32(av[j2]);
                Ah[buf ^ 1][ak + j2][am] = h;
                Al[buf ^ 1][ak + j2][am] = f2tf32(av[j2] - __uint_as_float(h));
                uint32_t hb = f2tf32(bv[j2]);
                Bh[buf ^ 1][ak + j2][am] = hb;
                Bl[buf ^ 1][ak + j2][am] = f2tf32(bv[j2] - __uint_as_float(hb));
            }
        }
        __syncthreads();
        buf ^= 1;
    }

    const float sc = *scale_ptr;
    #pragma unroll
    for (int mi = 0; mi < 4; mi++) {
        const int r0 = bm + wm + mi * 16 + g;
        #pragma unroll
        for (int ni = 0; ni < 4; ni++) {
            const int col = bn + wn + ni * 8 + tg * 2;
            *(float2*)(Cout + (size_t)r0 * N + col) =
                make_float2(acc[mi][ni][0] * sc, acc[mi][ni][1] * sc);
            *(float2*)(Cout + (size_t)(r0 + 8) * N + col) =
                make_float2(acc[mi][ni][2] * sc, acc[mi][ni][3] * sc);
        }
    }
}

// ---------------- launch ----------------
extern "C" void kernel_launch(void* const* d_in, const int* in_sizes, int n_in,
                              void* d_out, int out_size) {
    const float* x      = (const float*)d_in[0];
    const float* basis  = (const float*)d_in[1];
    const float* qc     = (const float*)d_in[2];
    const float* kc     = (const float*)d_in[3];
    const float* vc     = (const float*)d_in[4];
    const float* oc     = (const float*)d_in[5];
    const float* decay  = (const float*)d_in[6];
    const float* oscale = (const float*)d_in[7];
    float* out = (float*)d_out;

    weights_kernel<<<dim3(C_, 3), 1024>>>(basis, qc, kc, vc);
    qkv_mma_kernel<<<dim3((3 * C_) / 128, (B_ * T_) / 128), 256>>>(x);
    chunk_g_kernel<<<dim3(4, NCH, B_), 256>>>(decay);
    scan_kernel<<<128, 256>>>(decay);
    retr_kernel<<<dim3(NCH, B_), 256>>>(decay);
    oc_gemm_kernel<<<(B_ * T_) / 128, 256>>>(oc);
    out2_mma_kernel<<<dim3(V_ / 128, (B_ * T_) / 128), 256>>>(out, basis, oscale);
}

// round 5
// speedup vs baseline: 1.0463x; 1.0463x over previous
#include <cuda_runtime.h>
#include <math.h>
#include <stdint.h>

#define B_ 8
#define T_ 2048
#define V_ 1024
#define C_ 128
#define NB2 64   // 2*NB
#define S_ 64    // chunk size
#define NCH 32   // T_/S_
#define MT (B_ * T_)   // 16384

// ---------------- device scratch ----------------
__device__ float g_xh[V_ * MT];             // x hi, transposed [K][M]
__device__ float g_xl[V_ * MT];             // x lo, transposed [K][M]
__device__ float g_wh[V_ * 3 * C_];         // weights hi, [K][N] (K=V)
__device__ float g_wl[V_ * 3 * C_];         // weights lo
__device__ float g_qkv[MT * 3 * C_];        // (B*T, 384)
__device__ float g_r[MT * C_];              // retrieved (B*T, 128)
__device__ float g_r2[MT * NB2];            // retrieved @ oc  (B*T, 64)
__device__ float g_G[B_ * NCH * C_ * C_];   // per-chunk outer-product sums
__device__ float g_M[B_ * NCH * C_ * C_];   // chunk-boundary states

__device__ __forceinline__ float sigmoidf_(float x) { return 1.0f / (1.0f + expf(-x)); }

__device__ __forceinline__ uint32_t f2tf32(float x) {
    uint32_t r;
    asm("cvt.rna.tf32.f32 %0, %1;" : "=r"(r) : "f"(x));
    return r;
}

__device__ __forceinline__ void mma_tf32(float* c, const uint32_t* a, const uint32_t* b) {
    asm volatile(
        "mma.sync.aligned.m16n8k8.row.col.f32.tf32.tf32.f32 "
        "{%0,%1,%2,%3}, {%4,%5,%6,%7}, {%8,%9}, {%0,%1,%2,%3};"
        : "+f"(c[0]), "+f"(c[1]), "+f"(c[2]), "+f"(c[3])
        : "r"(a[0]), "r"(a[1]), "r"(a[2]), "r"(a[3]), "r"(b[0]), "r"(b[1]));
}

// ---------------- 0) convert x to tf32 hi/lo, transposed [K][M] ----------------
// grid: (MT/32, V/32), block 256. 32x32 tiles via smem.
__global__ __launch_bounds__(256) void cvt_x_kernel(const float* __restrict__ x) {
    __shared__ float th[32][33], tl[32][33];
    const int m0 = blockIdx.x * 32;
    const int k0 = blockIdx.y * 32;
    const int c = threadIdx.x & 31;
    const int r0 = threadIdx.x >> 5;   // 0..7

    #pragma unroll
    for (int u = 0; u < 4; u++) {
        const int r = r0 + u * 8;   // m within tile
        float v = x[(size_t)(m0 + r) * V_ + k0 + c];
        uint32_t h = f2tf32(v);
        th[r][c] = __uint_as_float(h);
        tl[r][c] = __uint_as_float(f2tf32(v - __uint_as_float(h)));
    }
    __syncthreads();
    #pragma unroll
    for (int u = 0; u < 4; u++) {
        const int r = r0 + u * 8;   // k within tile
        g_xh[(size_t)(k0 + r) * MT + m0 + c] = th[c][r];
        g_xl[(size_t)(k0 + r) * MT + m0 + c] = tl[c][r];
    }
}

// ---------------- 1) weights: basis @ coeffs^T (+ softmax over V), emit tf32 hi/lo ----------------
__global__ void weights_kernel(const float* __restrict__ basis,
                               const float* __restrict__ qc,
                               const float* __restrict__ kc,
                               const float* __restrict__ vc) {
    const int c = blockIdx.x;
    const int w = blockIdx.y;   // 0=q 1=k 2=v
    const int v = threadIdx.x;

    const float* coef = (w == 0 ? qc : (w == 1 ? kc : vc)) + c * NB2;
    __shared__ float scoef[NB2];
    __shared__ float red[32];
    __shared__ float sval;
    if (v < NB2) scoef[v] = coef[v];
    __syncthreads();

    float s = 0.f;
    const float4* brow = (const float4*)(basis + (size_t)v * NB2);
    #pragma unroll
    for (int jj = 0; jj < NB2 / 4; jj++) {
        float4 bv = brow[jj];
        s = fmaf(bv.x, scoef[4 * jj + 0], s);
        s = fmaf(bv.y, scoef[4 * jj + 1], s);
        s = fmaf(bv.z, scoef[4 * jj + 2], s);
        s = fmaf(bv.w, scoef[4 * jj + 3], s);
    }

    float m = s;
    #pragma unroll
    for (int o = 16; o; o >>= 1) m = fmaxf(m, __shfl_xor_sync(0xffffffffu, m, o));
    if ((v & 31) == 0) red[v >> 5] = m;
    __syncthreads();
    if (v < 32) {
        float t = red[v];
        #pragma unroll
        for (int o = 16; o; o >>= 1) t = fmaxf(t, __shfl_xor_sync(0xffffffffu, t, o));
        if (v == 0) sval = t;
    }
    __syncthreads();
    float e = expf(s - sval);

    float su = e;
    #pragma unroll
    for (int o = 16; o; o >>= 1) su += __shfl_xor_sync(0xffffffffu, su, o);
    if ((v & 31) == 0) red[v >> 5] = su;
    __syncthreads();
    if (v < 32) {
        float t = red[v];
        #pragma unroll
        for (int o = 16; o; o >>= 1) t += __shfl_xor_sync(0xffffffffu, t, o);
        if (v == 0) sval = t;
    }
    __syncthreads();

    const float val = e / sval;
    const uint32_t h = f2tf32(val);
    const size_t idx = (size_t)v * (3 * C_) + w * C_ + c;
    g_wh[idx] = __uint_as_float(h);
    g_wl[idx] = __uint_as_float(f2tf32(val - __uint_as_float(h)));
}

// ---------------- 2) QKV GEMM via tensor cores (tf32 x3), v3: preconverted operands ----------------
// g_qkv (16384x384) = x (16384x1024) @ w (1024x384), A from g_xh/g_xl [K][M], B from g_wh/g_wl [K][N].
// BM=128, BN=128, BK=8, 256 threads (8 warps), warp tile 64x32. Inner loop: LDS+MMA only.
#define QP 136  // conflict-free fragment LDS: bank = 8*tg + g, all distinct
__global__ __launch_bounds__(256) void qkv_mma_kernel() {
    constexpr int K = V_;       // 1024
    constexpr int N = 3 * C_;   // 384
    __shared__ uint32_t Ah[2][8][QP], Al[2][8][QP];
    __shared__ uint32_t Bh[2][8][QP], Bl[2][8][QP];

    const int tid = threadIdx.x;
    const int bm = blockIdx.y * 128;
    const int bn = blockIdx.x * 128;
    const int warp = tid >> 5, lane = tid & 31;
    const int g = lane >> 2, tg = lane & 3;
    const int wm = (warp >> 2) * 64;    // 0 or 64
    const int wn = (warp & 3) * 32;     // 0,32,64,96

    const int kr = tid >> 5;            // 0..7: k row within tile
    const int mq = tid & 31;            // 0..31: uint4 column

    const uint4* pAh = (const uint4*)(g_xh + (size_t)kr * MT + bm) + mq;
    const uint4* pAl = (const uint4*)(g_xl + (size_t)kr * MT + bm) + mq;
    const uint4* pBh = (const uint4*)(g_wh + (size_t)kr * N + bn) + mq;
    const uint4* pBl = (const uint4*)(g_wl + (size_t)kr * N + bn) + mq;
    const size_t strideA = (size_t)8 * MT / 4;   // uint4 units per 8-k step
    const size_t strideB = (size_t)8 * N / 4;

    float acc[4][4][4] = {};
    uint4 rah, ral, rbh, rbl;

    // prologue
    rah = pAh[0]; ral = pAl[0]; rbh = pBh[0]; rbl = pBl[0];
    *(uint4*)&Ah[0][kr][mq * 4] = rah;
    *(uint4*)&Al[0][kr][mq * 4] = ral;
    *(uint4*)&Bh[0][kr][mq * 4] = rbh;
    *(uint4*)&Bl[0][kr][mq * 4] = rbl;
    __syncthreads();

    int buf = 0;
    for (int k0 = 0; k0 < K; k0 += 8) {
        const bool has_next = (k0 + 8 < K);
        if (has_next) {
            const size_t off = (size_t)((k0 + 8) >> 3);
            rah = pAh[off * strideA]; ral = pAl[off * strideA];
            rbh = pBh[off * strideB]; rbl = pBl[off * strideB];
        }

        uint32_t bh[4][2], bl[4][2];
        #pragma unroll
        for (int ni = 0; ni < 4; ni++) {
            const int nc = wn + ni * 8 + g;
            bh[ni][0] = Bh[buf][tg][nc];
            bh[ni][1] = Bh[buf][tg + 4][nc];
            bl[ni][0] = Bl[buf][tg][nc];
            bl[ni][1] = Bl[buf][tg + 4][nc];
        }
        #pragma unroll
        for (int mi = 0; mi < 4; mi++) {
            const int mr = wm + mi * 16 + g;
            uint32_t ah[4], al[4];
            ah[0] = Ah[buf][tg][mr];     ah[1] = Ah[buf][tg][mr + 8];
            ah[2] = Ah[buf][tg + 4][mr]; ah[3] = Ah[buf][tg + 4][mr + 8];
            al[0] = Al[buf][tg][mr];     al[1] = Al[buf][tg][mr + 8];
            al[2] = Al[buf][tg + 4][mr]; al[3] = Al[buf][tg + 4][mr + 8];
            #pragma unroll
            for (int ni = 0; ni < 4; ni++) {
                mma_tf32(acc[mi][ni], al, bh[ni]);
                mma_tf32(acc[mi][ni], ah, bl[ni]);
                mma_tf32(acc[mi][ni], ah, bh[ni]);
            }
        }

        if (has_next) {
            *(uint4*)&Ah[buf ^ 1][kr][mq * 4] = rah;
            *(uint4*)&Al[buf ^ 1][kr][mq * 4] = ral;
            *(uint4*)&Bh[buf ^ 1][kr][mq * 4] = rbh;
            *(uint4*)&Bl[buf ^ 1][kr][mq * 4] = rbl;
        }
        __syncthreads();
        buf ^= 1;
    }

    // epilogue
    #pragma unroll
    for (int mi = 0; mi < 4; mi++) {
        const int r0 = bm + wm + mi * 16 + g;
        #pragma unroll
        for (int ni = 0; ni < 4; ni++) {
            const int col = bn + wn + ni * 8 + tg * 2;
            *(float2*)(g_qkv + (size_t)r0 * N + col)       = make_float2(acc[mi][ni][0], acc[mi][ni][1]);
            *(float2*)(g_qkv + (size_t)(r0 + 8) * N + col) = make_float2(acc[mi][ni][2], acc[mi][ni][3]);
        }
    }
}

// ---------------- 3a) per-chunk outer-product sums ----------------
__global__ __launch_bounds__(256) void chunk_g_kernel(const float* __restrict__ decay_ptr) {
    const int cg = blockIdx.x;
    const int j  = blockIdx.y;
    const int b  = blockIdx.z;
    const float dec = sigmoidf_(decay_ptr[0]);
    const float l2d = log2f(dec);

    __shared__ float Ks[32][128];
    __shared__ float Vs[32][32];

    const int tid = threadIdx.x;
    const int trow = tid >> 3;
    const int tcol = tid & 7;
    const int r  = tid >> 3;
    const int q8 = tid & 7;

    float acc[4][4] = {};
    const float* base = g_qkv + ((size_t)b * T_ + (size_t)j * S_) * (3 * C_);

    #pragma unroll
    for (int i0 = 0; i0 < S_; i0 += 32) {
        const float sc = exp2f((float)(S_ - 1 - (i0 + r)) * l2d);
        const float* krow = base + (size_t)(i0 + r) * (3 * C_) + C_;
        #pragma unroll
        for (int u = 0; u < 4; u++) {
            float4 kv = *(const float4*)(krow + (q8 + u * 8) * 4);
            Ks[r][(q8 + u * 8) * 4 + 0] = kv.x * sc;
            Ks[r][(q8 + u * 8) * 4 + 1] = kv.y * sc;
            Ks[r][(q8 + u * 8) * 4 + 2] = kv.z * sc;
            Ks[r][(q8 + u * 8) * 4 + 3] = kv.w * sc;
        }
        *(float4*)&Vs[r][q8 * 4] =
            *(const float4*)(base + (size_t)(i0 + r) * (3 * C_) + 2 * C_ + cg * 32 + q8 * 4);
        __syncthreads();
        #pragma unroll
        for (int ii = 0; ii < 32; ii++) {
            float4 a4 = *(const float4*)&Ks[ii][trow * 4];
            float4 b4 = *(const float4*)&Vs[ii][tcol * 4];
            float ar[4] = {a4.x, a4.y, a4.z, a4.w};
            float br[4] = {b4.x, b4.y, b4.z, b4.w};
            #pragma unroll
            for (int m = 0; m < 4; m++)
                #pragma unroll
                for (int n = 0; n < 4; n++)
                    acc[m][n] = fmaf(ar[m], br[n], acc[m][n]);
        }
        __syncthreads();
    }

    float* gout = g_G + ((size_t)(b * NCH + j) * C_ * C_) + cg * 32;
    #pragma unroll
    for (int m = 0; m < 4; m++)
        *(float4*)(gout + (size_t)(trow * 4 + m) * C_ + tcol * 4) =
            make_float4(acc[m][0], acc[m][1], acc[m][2], acc[m][3]);
}

// ---------------- 3b) scan with batched prefetch ----------------
__global__ void scan_kernel(const float* __restrict__ decay_ptr) {
    const int idx = blockIdx.x * blockDim.x + threadIdx.x;
    const int b = idx >> 12;
    const int e4 = idx & 4095;
    const float dec = sigmoidf_(decay_ptr[0]);
    const float dS = exp2f((float)S_ * log2f(dec));

    const float4* G = (const float4*)(g_G + (size_t)b * NCH * C_ * C_) + e4;
    float4* M = (float4*)(g_M + (size_t)b * NCH * C_ * C_) + e4;

    float4 m = make_float4(0.f, 0.f, 0.f, 0.f);
    #pragma unroll
    for (int jb = 0; jb < NCH; jb += 8) {
        float4 buf[8];
        #pragma unroll
        for (int u = 0; u < 8; u++) buf[u] = G[(size_t)(jb + u) * 4096];
        #pragma unroll
        for (int u = 0; u < 8; u++) {
            M[(size_t)(jb + u) * 4096] = m;
            m.x = fmaf(dS, m.x, buf[u].x);
            m.y = fmaf(dS, m.y, buf[u].y);
            m.z = fmaf(dS, m.z, buf[u].z);
            m.w = fmaf(dS, m.w, buf[u].w);
        }
    }
}

// ---------------- 3c) retrieval per chunk ----------------
__global__ __launch_bounds__(256) void retr_kernel(const float* __restrict__ decay_ptr) {
    const int j = blockIdx.x;
    const int b = blockIdx.y;
    const float dec = sigmoidf_(decay_ptr[0]);
    const float l2d = log2f(dec);

    __shared__ float Qs[32][64];
    __shared__ float Ks2[32][64];
    __shared__ float As[64][64];
    __shared__ float Vs[32][128];

    const int tid = threadIdx.x;
    const float* base = g_qkv + ((size_t)b * T_ + (size_t)j * S_) * (3 * C_);

    {
        const int ti = tid >> 4;
        const int ts = tid & 15;
        const int li = tid >> 2;
        const int lp = tid & 3;

        float acc[4][4] = {};
        for (int c0 = 0; c0 < C_; c0 += 32) {
            #pragma unroll
            for (int u = 0; u < 2; u++) {
                int c = lp * 8 + u * 4;
                float4 qv = *(const float4*)(base + (size_t)li * (3 * C_) + c0 + c);
                Qs[c + 0][li] = qv.x; Qs[c + 1][li] = qv.y;
                Qs[c + 2][li] = qv.z; Qs[c + 3][li] = qv.w;
                float4 kv = *(const float4*)(base + (size_t)li * (3 * C_) + C_ + c0 + c);
                Ks2[c + 0][li] = kv.x; Ks2[c + 1][li] = kv.y;
                Ks2[c + 2][li] = kv.z; Ks2[c + 3][li] = kv.w;
            }
            __syncthreads();
            #pragma unroll
            for (int cc = 0; cc < 32; cc++) {
                float4 a4 = *(const float4*)&Qs[cc][ti * 4];
                float4 b4 = *(const float4*)&Ks2[cc][ts * 4];
                float ar[4] = {a4.x, a4.y, a4.z, a4.w};
                float br[4] = {b4.x, b4.y, b4.z, b4.w};
                #pragma unroll
                for (int m = 0; m < 4; m++)
                    #pragma unroll
                    for (int n = 0; n < 4; n++)
                        acc[m][n] = fmaf(ar[m], br[n], acc[m][n]);
            }
            __syncthreads();
        }
        #pragma unroll
        for (int m = 0; m < 4; m++) {
            const int i = ti * 4 + m;
            #pragma unroll
            for (int n = 0; n < 4; n++) {
                const int s = ts * 4 + n;
                float v = 0.f;
                if (s < i) v = acc[m][n] * exp2f((float)(i - 1 - s) * l2d);
                As[s][i] = v;
            }
        }
    }
    __syncthreads();

    const int ti2 = tid >> 4;
    const int td  = tid & 15;
    const int lr  = tid >> 3;
    const int lq  = tid & 7;

    float accA[4][8] = {};
    float accM[4][8] = {};

    for (int s0 = 0; s0 < S_; s0 += 32) {
        #pragma unroll
        for (int u = 0; u < 4; u++) {
            int c4 = lq + u * 8;
            *(float4*)&Vs[lr][c4 * 4] =
                *(const float4*)(base + (size_t)(s0 + lr) * (3 * C_) + 2 * C_ + c4 * 4);
        }
        __syncthreads();
        #pragma unroll
        for (int ss = 0; ss < 32; ss++) {
            float4 a4 = *(const float4*)&As[s0 + ss][ti2 * 4];
            float4 b0 = *(const float4*)&Vs[ss][td * 8];
            float4 b1 = *(const float4*)&Vs[ss][td * 8 + 4];
            float ar[4] = {a4.x, a4.y, a4.z, a4.w};
            float br[8] = {b0.x, b0.y, b0.z, b0.w, b1.x, b1.y, b1.z, b1.w};
            #pragma unroll
            for (int m = 0; m < 4; m++)
                #pragma unroll
                for (int n = 0; n < 8; n++)
                    accA[m][n] = fmaf(ar[m], br[n], accA[m][n]);
        }
        __syncthreads();
    }

    const float* Mbase = g_M + (size_t)(b * NCH + j) * C_ * C_;
    {
        const int li = tid >> 2;
        const int lp = tid & 3;
        for (int c0 = 0; c0 < C_; c0 += 32) {
            #pragma unroll
            for (int u = 0; u < 2; u++) {
                int c = lp * 8 + u * 4;
                float4 qv = *(const float4*)(base + (size_t)li * (3 * C_) + c0 + c);
                Qs[c + 0][li] = qv.x; Qs[c + 1][li] = qv.y;
                Qs[c + 2][li] = qv.z; Qs[c + 3][li] = qv.w;
            }
            #pragma unroll
            for (int u = 0; u < 4; u++) {
                int c4 = lq + u * 8;
                *(float4*)&Vs[lr][c4 * 4] =
                    *(const float4*)(Mbase + (size_t)(c0 + lr) * C_ + c4 * 4);
            }
            __syncthreads();
            #pragma unroll
            for (int cc = 0; cc < 32; cc++) {
                float4 a4 = *(const float4*)&Qs[cc][ti2 * 4];
                float4 b0 = *(const float4*)&Vs[cc][td * 8];
                float4 b1 = *(const float4*)&Vs[cc][td * 8 + 4];
                float ar[4] = {a4.x, a4.y, a4.z, a4.w};
                float br[8] = {b0.x, b0.y, b0.z, b0.w, b1.x, b1.y, b1.z, b1.w};
                #pragma unroll
                for (int m = 0; m < 4; m++)
                    #pragma unroll
                    for (int n = 0; n < 8; n++)
                        accM[m][n] = fmaf(ar[m], br[n], accM[m][n]);
            }
            __syncthreads();
        }
    }

    float* rout = g_r + ((size_t)b * T_ + (size_t)j * S_) * C_;
    #pragma unroll
    for (int m = 0; m < 4; m++) {
        const int i = ti2 * 4 + m;
        const float di = exp2f((float)i * l2d);
        float o[8];
        #pragma unroll
        for (int n = 0; n < 8; n++) o[n] = fmaf(di, accM[m][n], accA[m][n]);
        *(float4*)(rout + (size_t)i * C_ + td * 8)     = make_float4(o[0], o[1], o[2], o[3]);
        *(float4*)(rout + (size_t)i * C_ + td * 8 + 4) = make_float4(o[4], o[5], o[6], o[7]);
    }
}

// ---------------- 4a) r2 = g_r (16384x128) @ oc (128x64) ----------------
__global__ __launch_bounds__(256) void oc_gemm_kernel(const float* __restrict__ oc) {
    constexpr int BK = 16;
    __shared__ float As[BK][C_];
    __shared__ float Bs[BK][NB2];

    const int tid = threadIdx.x;
    const int bm = blockIdx.x * 128;
    const int trow = tid >> 4;
    const int tcol = tid & 15;

    float acc[8][4] = {};

    for (int k0 = 0; k0 < C_; k0 += BK) {
        #pragma unroll
        for (int t = 0; t < 2; t++) {
            int idx = tid + t * 256;
            int m = idx >> 2, k4 = (idx & 3) * 4;
            float4 a4 = *(const float4*)(g_r + (size_t)(bm + m) * C_ + k0 + k4);
            As[k4 + 0][m] = a4.x; As[k4 + 1][m] = a4.y;
            As[k4 + 2][m] = a4.z; As[k4 + 3][m] = a4.w;
        }
        {
            int k = tid >> 4, n4 = (tid & 15) * 4;
            *(float4*)&Bs[k][n4] = *(const float4*)(oc + (size_t)(k0 + k) * NB2 + n4);
        }
        __syncthreads();
        #pragma unroll
        for (int kk = 0; kk < BK; kk++) {
            float ar[8], br[4];
            *(float4*)&ar[0] = *(const float4*)&As[kk][trow * 8];
            *(float4*)&ar[4] = *(const float4*)&As[kk][trow * 8 + 4];
            *(float4*)&br[0] = *(const float4*)&Bs[kk][tcol * 4];
            #pragma unroll
            for (int i = 0; i < 8; i++)
                #pragma unroll
                for (int jn = 0; jn < 4; jn++)
                    acc[i][jn] = fmaf(ar[i], br[jn], acc[i][jn]);
        }
        __syncthreads();
    }
    #pragma unroll
    for (int i = 0; i < 8; i++)
        *(float4*)(g_r2 + (size_t)(bm + trow * 8 + i) * NB2 + tcol * 4) =
            make_float4(acc[i][0], acc[i][1], acc[i][2], acc[i][3]);
}

// ---------------- 4b) out = g_r2 (16384x64) @ basis^T (64x1024) * scale, tf32 MMA ----------------
#define QP2 132
__global__ __launch_bounds__(256) void out2_mma_kernel(float* __restrict__ Cout,
                                                       const float* __restrict__ basis,
                                                       const float* __restrict__ scale_ptr) {
    constexpr int K = NB2;   // 64
    constexpr int N = V_;    // 1024
    __shared__ uint32_t Ah[2][8][QP2], Al[2][8][QP2];
    __shared__ uint32_t Bh[2][8][QP2], Bl[2][8][QP2];

    const int tid = threadIdx.x;
    const int bm = blockIdx.y * 128;
    const int bn = blockIdx.x * 128;
    const int warp = tid >> 5, lane = tid & 31;
    const int g = lane >> 2, tg = lane & 3;
    const int wm = (warp >> 2) * 64;
    const int wn = (warp & 3) * 32;

    const int am = tid >> 1, ak = (tid & 1) * 4;   // both operands: 128 rows x 8 k

    float acc[4][4][4] = {};
    float4 ra, rb;

    ra = *(const float4*)(g_r2 + (size_t)(bm + am) * K + ak);
    rb = *(const float4*)(basis + (size_t)(bn + am) * K + ak);
    {
        float av[4] = {ra.x, ra.y, ra.z, ra.w};
        float bv[4] = {rb.x, rb.y, rb.z, rb.w};
        #pragma unroll
        for (int j2 = 0; j2 < 4; j2++) {
            uint32_t h = f2tf32(av[j2]);
            Ah[0][ak + j2][am] = h;
            Al[0][ak + j2][am] = f2tf32(av[j2] - __uint_as_float(h));
            uint32_t hb = f2tf32(bv[j2]);
            Bh[0][ak + j2][am] = hb;
            Bl[0][ak + j2][am] = f2tf32(bv[j2] - __uint_as_float(hb));
        }
    }
    __syncthreads();

    int buf = 0;
    for (int k0 = 0; k0 < K; k0 += 8) {
        const bool has_next = (k0 + 8 < K);
        if (has_next) {
            ra = *(const float4*)(g_r2 + (size_t)(bm + am) * K + k0 + 8 + ak);
            rb = *(const float4*)(basis + (size_t)(bn + am) * K + k0 + 8 + ak);
        }

        uint32_t bh[4][2], bl[4][2];
        #pragma unroll
        for (int ni = 0; ni < 4; ni++) {
            const int nc = wn + ni * 8 + g;
            bh[ni][0] = Bh[buf][tg][nc];
            bh[ni][1] = Bh[buf][tg + 4][nc];
            bl[ni][0] = Bl[buf][tg][nc];
            bl[ni][1] = Bl[buf][tg + 4][nc];
        }
        #pragma unroll
        for (int mi = 0; mi < 4; mi++) {
            const int mr = wm + mi * 16 + g;
            uint32_t ah[4], al[4];
            ah[0] = Ah[buf][tg][mr];     ah[1] = Ah[buf][tg][mr + 8];
            ah[2] = Ah[buf][tg + 4][mr]; ah[3] = Ah[buf][tg + 4][mr + 8];
            al[0] = Al[buf][tg][mr];     al[1] = Al[buf][tg][mr + 8];
            al[2] = Al[buf][tg + 4][mr]; al[3] = Al[buf][tg + 4][mr + 8];
            #pragma unroll
            for (int ni = 0; ni < 4; ni++) {
                mma_tf32(acc[mi][ni], al, bh[ni]);
                mma_tf32(acc[mi][ni], ah, bl[ni]);
                mma_tf32(acc[mi][ni], ah, bh[ni]);
            }
        }

        if (has_next) {
            float av[4] = {ra.x, ra.y, ra.z, ra.w};
            float bv[4] = {rb.x, rb.y, rb.z, rb.w};
            #pragma unroll
            for (int j2 = 0; j2 < 4; j2++) {
                uint32_t h = f2tf32(av[j2]);
                Ah[buf ^ 1][ak + j2][am] = h;
                Al[buf ^ 1][ak + j2][am] = f2tf32(av[j2] - __uint_as_float(h));
                uint32_t hb = f2tf32(bv[j2]);
                Bh[buf ^ 1][ak + j2][am] = hb;
                Bl[buf ^ 1][ak + j2][am] = f2tf32(bv[j2] - __uint_as_float(hb));
            }
        }
        __syncthreads();
        buf ^= 1;
    }

    const float sc = *scale_ptr;
    #pragma unroll
    for (int mi = 0; mi < 4; mi++) {
        const int r0 = bm + wm + mi * 16 + g;
        #pragma unroll
        for (int ni = 0; ni < 4; ni++) {
            const int col = bn + wn + ni * 8 + tg * 2;
            *(float2*)(Cout + (size_t)r0 * N + col) =
                make_float2(acc[mi][ni][0] * sc, acc[mi][ni][1] * sc);
            *(float2*)(Cout + (size_t)(r0 + 8) * N + col) =
                make_float2(acc[mi][ni][2] * sc, acc[mi][ni][3] * sc);
        }
    }
}

// ---------------- launch ----------------
extern "C" void kernel_launch(void* const* d_in, const int* in_sizes, int n_in,
                              void* d_out, int out_size) {
    const float* x      = (const float*)d_in[0];
    const float* basis  = (const float*)d_in[1];
    const float* qc     = (const float*)d_in[2];
    const float* kc     = (const float*)d_in[3];
    const float* vc     = (const float*)d_in[4];
    const float* oc     = (const float*)d_in[5];
    const float* decay  = (const float*)d_in[6];
    const float* oscale = (const float*)d_in[7];
    float* out = (float*)d_out;

    cvt_x_kernel<<<dim3(MT / 32, V_ / 32), 256>>>(x);
    weights_kernel<<<dim3(C_, 3), 1024>>>(basis, qc, kc, vc);
    qkv_mma_kernel<<<dim3((3 * C_) / 128, MT / 128), 256>>>();
    chunk_g_kernel<<<dim3(4, NCH, B_), 256>>>(decay);
    scan_kernel<<<128, 256>>>(decay);
    retr_kernel<<<dim3(NCH, B_), 256>>>(decay);
    oc_gemm_kernel<<<MT / 128, 256>>>(oc);
    out2_mma_kernel<<<dim3(V_ / 128, MT / 128), 256>>>(out, basis, oscale);
}

// round 6
// speedup vs baseline: 1.4566x; 1.3922x over previous
#include <cuda_runtime.h>
#include <cuda_bf16.h>
#include <math.h>
#include <stdint.h>

#define B_ 8
#define T_ 2048
#define V_ 1024
#define C_ 128
#define NB2 64   // 2*NB
#define S_ 64    // chunk size
#define NCH 32   // T_/S_
#define MT (B_ * T_)   // 16384

// ---------------- device scratch ----------------
__device__ uint32_t g_xh2[(V_ / 2) * MT];       // x hi bf16x2, [K/2][M]
__device__ uint32_t g_xl2[(V_ / 2) * MT];       // x lo bf16x2, [K/2][M]
__device__ uint32_t g_wh2[(V_ / 2) * 3 * C_];   // weights hi bf16x2, [K/2][N]
__device__ uint32_t g_wl2[(V_ / 2) * 3 * C_];   // weights lo bf16x2
__device__ float g_qkv[MT * 3 * C_];            // (B*T, 384)
__device__ float g_r[MT * C_];                  // retrieved (B*T, 128)
__device__ float g_r2[MT * NB2];                // retrieved @ oc  (B*T, 64)
__device__ float g_G[B_ * NCH * C_ * C_];       // per-chunk outer-product sums
__device__ float g_M[B_ * NCH * C_ * C_];       // chunk-boundary states

__device__ __forceinline__ float sigmoidf_(float x) { return 1.0f / (1.0f + expf(-x)); }

__device__ __forceinline__ uint32_t f2tf32(float x) {
    uint32_t r;
    asm("cvt.rna.tf32.f32 %0, %1;" : "=r"(r) : "f"(x));
    return r;
}

__device__ __forceinline__ void mma_tf32(float* c, const uint32_t* a, const uint32_t* b) {
    asm volatile(
        "mma.sync.aligned.m16n8k8.row.col.f32.tf32.tf32.f32 "
        "{%0,%1,%2,%3}, {%4,%5,%6,%7}, {%8,%9}, {%0,%1,%2,%3};"
        : "+f"(c[0]), "+f"(c[1]), "+f"(c[2]), "+f"(c[3])
        : "r"(a[0]), "r"(a[1]), "r"(a[2]), "r"(a[3]), "r"(b[0]), "r"(b[1]));
}

__device__ __forceinline__ void mma_bf16(float* c, const uint32_t* a, const uint32_t* b) {
    asm volatile(
        "mma.sync.aligned.m16n8k16.row.col.f32.bf16.bf16.f32 "
        "{%0,%1,%2,%3}, {%4,%5,%6,%7}, {%8,%9}, {%0,%1,%2,%3};"
        : "+f"(c[0]), "+f"(c[1]), "+f"(c[2]), "+f"(c[3])
        : "r"(a[0]), "r"(a[1]), "r"(a[2]), "r"(a[3]), "r"(b[0]), "r"(b[1]));
}

// ---------------- 0) convert x to bf16 hi/lo, transposed packed [K/2][M] ----------------
// grid: (MT/32, V/32), block 256.
__global__ __launch_bounds__(256) void cvt_x_kernel(const float* __restrict__ x) {
    __shared__ unsigned short sh[32][33], sl[32][33];
    const int m0 = blockIdx.x * 32;
    const int k0 = blockIdx.y * 32;
    const int c = threadIdx.x & 31;
    const int r0 = threadIdx.x >> 5;   // 0..7

    #pragma unroll
    for (int u = 0; u < 4; u++) {
        const int m = r0 + u * 8;
        float v = x[(size_t)(m0 + m) * V_ + k0 + c];
        __nv_bfloat16 h = __float2bfloat16_rn(v);
        float hf = __bfloat162float(h);
        __nv_bfloat16 l = __float2bfloat16_rn(v - hf);
        sh[m][c] = __bfloat16_as_ushort(h);
        sl[m][c] = __bfloat16_as_ushort(l);
    }
    __syncthreads();

    const int m = threadIdx.x & 31;
    const int k2r = threadIdx.x >> 5;  // 0..7
    #pragma unroll
    for (int u = 0; u < 2; u++) {
        const int k2 = k2r + u * 8;    // 0..15
        uint32_t ph = (uint32_t)sh[m][2 * k2] | ((uint32_t)sh[m][2 * k2 + 1] << 16);
        uint32_t pl = (uint32_t)sl[m][2 * k2] | ((uint32_t)sl[m][2 * k2 + 1] << 16);
        g_xh2[(size_t)(k0 / 2 + k2) * MT + m0 + m] = ph;
        g_xl2[(size_t)(k0 / 2 + k2) * MT + m0 + m] = pl;
    }
}

// ---------------- 1) weights: basis @ coeffs^T (+ softmax over V), emit bf16 hi/lo ----------------
__global__ void weights_kernel(const float* __restrict__ basis,
                               const float* __restrict__ qc,
                               const float* __restrict__ kc,
                               const float* __restrict__ vc) {
    const int c = blockIdx.x;
    const int w = blockIdx.y;   // 0=q 1=k 2=v
    const int v = threadIdx.x;

    const float* coef = (w == 0 ? qc : (w == 1 ? kc : vc)) + c * NB2;
    __shared__ float scoef[NB2];
    __shared__ float red[32];
    __shared__ float sval;
    if (v < NB2) scoef[v] = coef[v];
    __syncthreads();

    float s = 0.f;
    const float4* brow = (const float4*)(basis + (size_t)v * NB2);
    #pragma unroll
    for (int jj = 0; jj < NB2 / 4; jj++) {
        float4 bv = brow[jj];
        s = fmaf(bv.x, scoef[4 * jj + 0], s);
        s = fmaf(bv.y, scoef[4 * jj + 1], s);
        s = fmaf(bv.z, scoef[4 * jj + 2], s);
        s = fmaf(bv.w, scoef[4 * jj + 3], s);
    }

    float m = s;
    #pragma unroll
    for (int o = 16; o; o >>= 1) m = fmaxf(m, __shfl_xor_sync(0xffffffffu, m, o));
    if ((v & 31) == 0) red[v >> 5] = m;
    __syncthreads();
    if (v < 32) {
        float t = red[v];
        #pragma unroll
        for (int o = 16; o; o >>= 1) t = fmaxf(t, __shfl_xor_sync(0xffffffffu, t, o));
        if (v == 0) sval = t;
    }
    __syncthreads();
    float e = expf(s - sval);

    float su = e;
    #pragma unroll
    for (int o = 16; o; o >>= 1) su += __shfl_xor_sync(0xffffffffu, su, o);
    if ((v & 31) == 0) red[v >> 5] = su;
    __syncthreads();
    if (v < 32) {
        float t = red[v];
        #pragma unroll
        for (int o = 16; o; o >>= 1) t += __shfl_xor_sync(0xffffffffu, t, o);
        if (v == 0) sval = t;
    }
    __syncthreads();

    const float val = e / sval;
    __nv_bfloat16 h = __float2bfloat16_rn(val);
    __nv_bfloat16 l = __float2bfloat16_rn(val - __bfloat162float(h));

    constexpr int N = 3 * C_;
    const int n = w * C_ + c;
    const size_t us_idx = ((size_t)(v >> 1) * N + n) * 2 + (v & 1);
    ((unsigned short*)g_wh2)[us_idx] = __bfloat16_as_ushort(h);
    ((unsigned short*)g_wl2)[us_idx] = __bfloat16_as_ushort(l);
}

// ---------------- 2) QKV GEMM via bf16x3 tensor-core MMA ----------------
// g_qkv (16384x384) = x (16384x1024) @ w (1024x384)
// BM=128, BN=128, BK=16 (8 packed k2-rows), 256 threads, warp tile 64x32.
#define QP 136  // conflict-free fragment LDS: bank = 8*tg + g, all distinct
__global__ __launch_bounds__(256) void qkv_mma_kernel() {
    constexpr int K2 = V_ / 2;  // 512 packed rows
    constexpr int N = 3 * C_;   // 384
    __shared__ uint32_t Ah[2][8][QP], Al[2][8][QP];
    __shared__ uint32_t Bh[2][8][QP], Bl[2][8][QP];

    const int tid = threadIdx.x;
    const int bm = blockIdx.y * 128;
    const int bn = blockIdx.x * 128;
    const int warp = tid >> 5, lane = tid & 31;
    const int g = lane >> 2, tg = lane & 3;
    const int wm = (warp >> 2) * 64;    // 0 or 64
    const int wn = (warp & 3) * 32;     // 0,32,64,96

    const int kr = tid >> 5;            // 0..7: packed k2 row within tile
    const int mq = tid & 31;            // uint4 column

    const uint4* pAh = (const uint4*)(g_xh2 + (size_t)kr * MT + bm) + mq;
    const uint4* pAl = (const uint4*)(g_xl2 + (size_t)kr * MT + bm) + mq;
    const uint4* pBh = (const uint4*)(g_wh2 + (size_t)kr * N + bn) + mq;
    const uint4* pBl = (const uint4*)(g_wl2 + (size_t)kr * N + bn) + mq;
    const size_t strideA = (size_t)8 * MT / 4;   // uint4 units per tile step
    const size_t strideB = (size_t)8 * N / 4;

    float acc[4][4][4] = {};
    uint4 rah, ral, rbh, rbl;

    // prologue
    rah = pAh[0]; ral = pAl[0]; rbh = pBh[0]; rbl = pBl[0];
    *(uint4*)&Ah[0][kr][mq * 4] = rah;
    *(uint4*)&Al[0][kr][mq * 4] = ral;
    *(uint4*)&Bh[0][kr][mq * 4] = rbh;
    *(uint4*)&Bl[0][kr][mq * 4] = rbl;
    __syncthreads();

    int buf = 0;
    for (int k0 = 0; k0 < K2; k0 += 8) {
        const bool has_next = (k0 + 8 < K2);
        if (has_next) {
            const size_t off = (size_t)((k0 + 8) >> 3);
            rah = pAh[off * strideA]; ral = pAl[off * strideA];
            rbh = pBh[off * strideB]; rbl = pBl[off * strideB];
        }

        uint32_t bh[4][2], bl[4][2];
        #pragma unroll
        for (int ni = 0; ni < 4; ni++) {
            const int nc = wn + ni * 8 + g;
            bh[ni][0] = Bh[buf][tg][nc];
            bh[ni][1] = Bh[buf][tg + 4][nc];
            bl[ni][0] = Bl[buf][tg][nc];
            bl[ni][1] = Bl[buf][tg + 4][nc];
        }
        #pragma unroll
        for (int mi = 0; mi < 4; mi++) {
            const int mr = wm + mi * 16 + g;
            uint32_t ah[4], al[4];
            ah[0] = Ah[buf][tg][mr];     ah[1] = Ah[buf][tg][mr + 8];
            ah[2] = Ah[buf][tg + 4][mr]; ah[3] = Ah[buf][tg + 4][mr + 8];
            al[0] = Al[buf][tg][mr];     al[1] = Al[buf][tg][mr + 8];
            al[2] = Al[buf][tg + 4][mr]; al[3] = Al[buf][tg + 4][mr + 8];
            #pragma unroll
            for (int ni = 0; ni < 4; ni++) {
                mma_bf16(acc[mi][ni], al, bh[ni]);
                mma_bf16(acc[mi][ni], ah, bl[ni]);
                mma_bf16(acc[mi][ni], ah, bh[ni]);
            }
        }

        if (has_next) {
            *(uint4*)&Ah[buf ^ 1][kr][mq * 4] = rah;
            *(uint4*)&Al[buf ^ 1][kr][mq * 4] = ral;
            *(uint4*)&Bh[buf ^ 1][kr][mq * 4] = rbh;
            *(uint4*)&Bl[buf ^ 1][kr][mq * 4] = rbl;
        }
        __syncthreads();
        buf ^= 1;
    }

    // epilogue
    #pragma unroll
    for (int mi = 0; mi < 4; mi++) {
        const int r0 = bm + wm + mi * 16 + g;
        #pragma unroll
        for (int ni = 0; ni < 4; ni++) {
            const int col = bn + wn + ni * 8 + tg * 2;
            *(float2*)(g_qkv + (size_t)r0 * (3 * C_) + col)       = make_float2(acc[mi][ni][0], acc[mi][ni][1]);
            *(float2*)(g_qkv + (size_t)(r0 + 8) * (3 * C_) + col) = make_float2(acc[mi][ni][2], acc[mi][ni][3]);
        }
    }
}

// ---------------- 3a) per-chunk outer-product sums ----------------
__global__ __launch_bounds__(256) void chunk_g_kernel(const float* __restrict__ decay_ptr) {
    const int cg = blockIdx.x;
    const int j  = blockIdx.y;
    const int b  = blockIdx.z;
    const float dec = sigmoidf_(decay_ptr[0]);
    const float l2d = log2f(dec);

    __shared__ float Ks[32][128];
    __shared__ float Vs[32][32];

    const int tid = threadIdx.x;
    const int trow = tid >> 3;
    const int tcol = tid & 7;
    const int r  = tid >> 3;
    const int q8 = tid & 7;

    float acc[4][4] = {};
    const float* base = g_qkv + ((size_t)b * T_ + (size_t)j * S_) * (3 * C_);

    #pragma unroll
    for (int i0 = 0; i0 < S_; i0 += 32) {
        const float sc = exp2f((float)(S_ - 1 - (i0 + r)) * l2d);
        const float* krow = base + (size_t)(i0 + r) * (3 * C_) + C_;
        #pragma unroll
        for (int u = 0; u < 4; u++) {
            float4 kv = *(const float4*)(krow + (q8 + u * 8) * 4);
            Ks[r][(q8 + u * 8) * 4 + 0] = kv.x * sc;
            Ks[r][(q8 + u * 8) * 4 + 1] = kv.y * sc;
            Ks[r][(q8 + u * 8) * 4 + 2] = kv.z * sc;
            Ks[r][(q8 + u * 8) * 4 + 3] = kv.w * sc;
        }
        *(float4*)&Vs[r][q8 * 4] =
            *(const float4*)(base + (size_t)(i0 + r) * (3 * C_) + 2 * C_ + cg * 32 + q8 * 4);
        __syncthreads();
        #pragma unroll
        for (int ii = 0; ii < 32; ii++) {
            float4 a4 = *(const float4*)&Ks[ii][trow * 4];
            float4 b4 = *(const float4*)&Vs[ii][tcol * 4];
            float ar[4] = {a4.x, a4.y, a4.z, a4.w};
            float br[4] = {b4.x, b4.y, b4.z, b4.w};
            #pragma unroll
            for (int m = 0; m < 4; m++)
                #pragma unroll
                for (int n = 0; n < 4; n++)
                    acc[m][n] = fmaf(ar[m], br[n], acc[m][n]);
        }
        __syncthreads();
    }

    float* gout = g_G + ((size_t)(b * NCH + j) * C_ * C_) + cg * 32;
    #pragma unroll
    for (int m = 0; m < 4; m++)
        *(float4*)(gout + (size_t)(trow * 4 + m) * C_ + tcol * 4) =
            make_float4(acc[m][0], acc[m][1], acc[m][2], acc[m][3]);
}

// ---------------- 3b) scan with batched prefetch ----------------
__global__ void scan_kernel(const float* __restrict__ decay_ptr) {
    const int idx = blockIdx.x * blockDim.x + threadIdx.x;
    const int b = idx >> 12;
    const int e4 = idx & 4095;
    const float dec = sigmoidf_(decay_ptr[0]);
    const float dS = exp2f((float)S_ * log2f(dec));

    const float4* G = (const float4*)(g_G + (size_t)b * NCH * C_ * C_) + e4;
    float4* M = (float4*)(g_M + (size_t)b * NCH * C_ * C_) + e4;

    float4 m = make_float4(0.f, 0.f, 0.f, 0.f);
    #pragma unroll
    for (int jb = 0; jb < NCH; jb += 8) {
        float4 buf[8];
        #pragma unroll
        for (int u = 0; u < 8; u++) buf[u] = G[(size_t)(jb + u) * 4096];
        #pragma unroll
        for (int u = 0; u < 8; u++) {
            M[(size_t)(jb + u) * 4096] = m;
            m.x = fmaf(dS, m.x, buf[u].x);
            m.y = fmaf(dS, m.y, buf[u].y);
            m.z = fmaf(dS, m.z, buf[u].z);
            m.w = fmaf(dS, m.w, buf[u].w);
        }
    }
}

// ---------------- 3c) retrieval per chunk ----------------
__global__ __launch_bounds__(256) void retr_kernel(const float* __restrict__ decay_ptr) {
    const int j = blockIdx.x;
    const int b = blockIdx.y;
    const float dec = sigmoidf_(decay_ptr[0]);
    const float l2d = log2f(dec);

    __shared__ float Qs[32][64];
    __shared__ float Ks2[32][64];
    __shared__ float As[64][64];
    __shared__ float Vs[32][128];

    const int tid = threadIdx.x;
    const float* base = g_qkv + ((size_t)b * T_ + (size_t)j * S_) * (3 * C_);

    {
        const int ti = tid >> 4;
        const int ts = tid & 15;
        const int li = tid >> 2;
        const int lp = tid & 3;

        float acc[4][4] = {};
        for (int c0 = 0; c0 < C_; c0 += 32) {
            #pragma unroll
            for (int u = 0; u < 2; u++) {
                int c = lp * 8 + u * 4;
                float4 qv = *(const float4*)(base + (size_t)li * (3 * C_) + c0 + c);
                Qs[c + 0][li] = qv.x; Qs[c + 1][li] = qv.y;
                Qs[c + 2][li] = qv.z; Qs[c + 3][li] = qv.w;
                float4 kv = *(const float4*)(base + (size_t)li * (3 * C_) + C_ + c0 + c);
                Ks2[c + 0][li] = kv.x; Ks2[c + 1][li] = kv.y;
                Ks2[c + 2][li] = kv.z; Ks2[c + 3][li] = kv.w;
            }
            __syncthreads();
            #pragma unroll
            for (int cc = 0; cc < 32; cc++) {
                float4 a4 = *(const float4*)&Qs[cc][ti * 4];
                float4 b4 = *(const float4*)&Ks2[cc][ts * 4];
                float ar[4] = {a4.x, a4.y, a4.z, a4.w};
                float br[4] = {b4.x, b4.y, b4.z, b4.w};
                #pragma unroll
                for (int m = 0; m < 4; m++)
                    #pragma unroll
                    for (int n = 0; n < 4; n++)
                        acc[m][n] = fmaf(ar[m], br[n], acc[m][n]);
            }
            __syncthreads();
        }
        #pragma unroll
        for (int m = 0; m < 4; m++) {
            const int i = ti * 4 + m;
            #pragma unroll
            for (int n = 0; n < 4; n++) {
                const int s = ts * 4 + n;
                float v = 0.f;
                if (s < i) v = acc[m][n] * exp2f((float)(i - 1 - s) * l2d);
                As[s][i] = v;
            }
        }
    }
    __syncthreads();

    const int ti2 = tid >> 4;
    const int td  = tid & 15;
    const int lr  = tid >> 3;
    const int lq  = tid & 7;

    float accA[4][8] = {};
    float accM[4][8] = {};

    for (int s0 = 0; s0 < S_; s0 += 32) {
        #pragma unroll
        for (int u = 0; u < 4; u++) {
            int c4 = lq + u * 8;
            *(float4*)&Vs[lr][c4 * 4] =
                *(const float4*)(base + (size_t)(s0 + lr) * (3 * C_) + 2 * C_ + c4 * 4);
        }
        __syncthreads();
        #pragma unroll
        for (int ss = 0; ss < 32; ss++) {
            float4 a4 = *(const float4*)&As[s0 + ss][ti2 * 4];
            float4 b0 = *(const float4*)&Vs[ss][td * 8];
            float4 b1 = *(const float4*)&Vs[ss][td * 8 + 4];
            float ar[4] = {a4.x, a4.y, a4.z, a4.w};
            float br[8] = {b0.x, b0.y, b0.z, b0.w, b1.x, b1.y, b1.z, b1.w};
            #pragma unroll
            for (int m = 0; m < 4; m++)
                #pragma unroll
                for (int n = 0; n < 8; n++)
                    accA[m][n] = fmaf(ar[m], br[n], accA[m][n]);
        }
        __syncthreads();
    }

    const float* Mbase = g_M + (size_t)(b * NCH + j) * C_ * C_;
    {
        const int li = tid >> 2;
        const int lp = tid & 3;
        for (int c0 = 0; c0 < C_; c0 += 32) {
            #pragma unroll
            for (int u = 0; u < 2; u++) {
                int c = lp * 8 + u * 4;
                float4 qv = *(const float4*)(base + (size_t)li * (3 * C_) + c0 + c);
                Qs[c + 0][li] = qv.x; Qs[c + 1][li] = qv.y;
                Qs[c + 2][li] = qv.z; Qs[c + 3][li] = qv.w;
            }
            #pragma unroll
            for (int u = 0; u < 4; u++) {
                int c4 = lq + u * 8;
                *(float4*)&Vs[lr][c4 * 4] =
                    *(const float4*)(Mbase + (size_t)(c0 + lr) * C_ + c4 * 4);
            }
            __syncthreads();
            #pragma unroll
            for (int cc = 0; cc < 32; cc++) {
                float4 a4 = *(const float4*)&Qs[cc][ti2 * 4];
                float4 b0 = *(const float4*)&Vs[cc][td * 8];
                float4 b1 = *(const float4*)&Vs[cc][td * 8 + 4];
                float ar[4] = {a4.x, a4.y, a4.z, a4.w};
                float br[8] = {b0.x, b0.y, b0.z, b0.w, b1.x, b1.y, b1.z, b1.w};
                #pragma unroll
                for (int m = 0; m < 4; m++)
                    #pragma unroll
                    for (int n = 0; n < 8; n++)
                        accM[m][n] = fmaf(ar[m], br[n], accM[m][n]);
            }
            __syncthreads();
        }
    }

    float* rout = g_r + ((size_t)b * T_ + (size_t)j * S_) * C_;
    #pragma unroll
    for (int m = 0; m < 4; m++) {
        const int i = ti2 * 4 + m;
        const float di = exp2f((float)i * l2d);
        float o[8];
        #pragma unroll
        for (int n = 0; n < 8; n++) o[n] = fmaf(di, accM[m][n], accA[m][n]);
        *(float4*)(rout + (size_t)i * C_ + td * 8)     = make_float4(o[0], o[1], o[2], o[3]);
        *(float4*)(rout + (size_t)i * C_ + td * 8 + 4) = make_float4(o[4], o[5], o[6], o[7]);
    }
}

// ---------------- 4a) r2 = g_r (16384x128) @ oc (128x64) ----------------
__global__ __launch_bounds__(256) void oc_gemm_kernel(const float* __restrict__ oc) {
    constexpr int BK = 16;
    __shared__ float As[BK][C_];
    __shared__ float Bs[BK][NB2];

    const int tid = threadIdx.x;
    const int bm = blockIdx.x * 128;
    const int trow = tid >> 4;
    const int tcol = tid & 15;

    float acc[8][4] = {};

    for (int k0 = 0; k0 < C_; k0 += BK) {
        #pragma unroll
        for (int t = 0; t < 2; t++) {
            int idx = tid + t * 256;
            int m = idx >> 2, k4 = (idx & 3) * 4;
            float4 a4 = *(const float4*)(g_r + (size_t)(bm + m) * C_ + k0 + k4);
            As[k4 + 0][m] = a4.x; As[k4 + 1][m] = a4.y;
            As[k4 + 2][m] = a4.z; As[k4 + 3][m] = a4.w;
        }
        {
            int k = tid >> 4, n4 = (tid & 15) * 4;
            *(float4*)&Bs[k][n4] = *(const float4*)(oc + (size_t)(k0 + k) * NB2 + n4);
        }
        __syncthreads();
        #pragma unroll
        for (int kk = 0; kk < BK; kk++) {
            float ar[8], br[4];
            *(float4*)&ar[0] = *(const float4*)&As[kk][trow * 8];
            *(float4*)&ar[4] = *(const float4*)&As[kk][trow * 8 + 4];
            *(float4*)&br[0] = *(const float4*)&Bs[kk][tcol * 4];
            #pragma unroll
            for (int i = 0; i < 8; i++)
                #pragma unroll
                for (int jn = 0; jn < 4; jn++)
                    acc[i][jn] = fmaf(ar[i], br[jn], acc[i][jn]);
        }
        __syncthreads();
    }
    #pragma unroll
    for (int i = 0; i < 8; i++)
        *(float4*)(g_r2 + (size_t)(bm + trow * 8 + i) * NB2 + tcol * 4) =
            make_float4(acc[i][0], acc[i][1], acc[i][2], acc[i][3]);
}

// ---------------- 4b) out = g_r2 (16384x64) @ basis^T (64x1024) * scale, tf32 MMA ----------------
#define QP2 132
__global__ __launch_bounds__(256) void out2_mma_kernel(float* __restrict__ Cout,
                                                       const float* __restrict__ basis,
                                                       const float* __restrict__ scale_ptr) {
    constexpr int K = NB2;   // 64
    constexpr int N = V_;    // 1024
    __shared__ uint32_t Ah[2][8][QP2], Al[2][8][QP2];
    __shared__ uint32_t Bh[2][8][QP2], Bl[2][8][QP2];

    const int tid = threadIdx.x;
    const int bm = blockIdx.y * 128;
    const int bn = blockIdx.x * 128;
    const int warp = tid >> 5, lane = tid & 31;
    const int g = lane >> 2, tg = lane & 3;
    const int wm = (warp >> 2) * 64;
    const int wn = (warp & 3) * 32;

    const int am = tid >> 1, ak = (tid & 1) * 4;

    float acc[4][4][4] = {};
    float4 ra, rb;

    ra = *(const float4*)(g_r2 + (size_t)(bm + am) * K + ak);
    rb = *(const float4*)(basis + (size_t)(bn + am) * K + ak);
    {
        float av[4] = {ra.x, ra.y, ra.z, ra.w};
        float bv[4] = {rb.x, rb.y, rb.z, rb.w};
        #pragma unroll
        for (int j2 = 0; j2 < 4; j2++) {
            uint32_t h = f2tf32(av[j2]);
            Ah[0][ak + j2][am] = h;
            Al[0][ak + j2][am] = f2tf32(av[j2] - __uint_as_float(h));
            uint32_t hb = f2tf32(bv[j2]);
            Bh[0][ak + j2][am] = hb;
            Bl[0][ak + j2][am] = f2tf32(bv[j2] - __uint_as_float(hb));
        }
    }
    __syncthreads();

    int buf = 0;
    for (int k0 = 0; k0 < K; k0 += 8) {
        const bool has_next = (k0 + 8 < K);
        if (has_next) {
            ra = *(const float4*)(g_r2 + (size_t)(bm + am) * K + k0 + 8 + ak);
            rb = *(const float4*)(basis + (size_t)(bn + am) * K + k0 + 8 + ak);
        }

        uint32_t bh[4][2], bl[4][2];
        #pragma unroll
        for (int ni = 0; ni < 4; ni++) {
            const int nc = wn + ni * 8 + g;
            bh[ni][0] = Bh[buf][tg][nc];
            bh[ni][1] = Bh[buf][tg + 4][nc];
            bl[ni][0] = Bl[buf][tg][nc];
            bl[ni][1] = Bl[buf][tg + 4][nc];
        }
        #pragma unroll
        for (int mi = 0; mi < 4; mi++) {
            const int mr = wm + mi * 16 + g;
            uint32_t ah[4], al[4];
            ah[0] = Ah[buf][tg][mr];     ah[1] = Ah[buf][tg][mr + 8];
            ah[2] = Ah[buf][tg + 4][mr]; ah[3] = Ah[buf][tg + 4][mr + 8];
            al[0] = Al[buf][tg][mr];     al[1] = Al[buf][tg][mr + 8];
            al[2] = Al[buf][tg + 4][mr]; al[3] = Al[buf][tg + 4][mr + 8];
            #pragma unroll
            for (int ni = 0; ni < 4; ni++) {
                mma_tf32(acc[mi][ni], al, bh[ni]);
                mma_tf32(acc[mi][ni], ah, bl[ni]);
                mma_tf32(acc[mi][ni], ah, bh[ni]);
            }
        }

        if (has_next) {
            float av[4] = {ra.x, ra.y, ra.z, ra.w};
            float bv[4] = {rb.x, rb.y, rb.z, rb.w};
            #pragma unroll
            for (int j2 = 0; j2 < 4; j2++) {
                uint32_t h = f2tf32(av[j2]);
                Ah[buf ^ 1][ak + j2][am] = h;
                Al[buf ^ 1][ak + j2][am] = f2tf32(av[j2] - __uint_as_float(h));
                uint32_t hb = f2tf32(bv[j2]);
                Bh[buf ^ 1][ak + j2][am] = hb;
                Bl[buf ^ 1][ak + j2][am] = f2tf32(bv[j2] - __uint_as_float(hb));
            }
        }
        __syncthreads();
        buf ^= 1;
    }

    const float sc = *scale_ptr;
    #pragma unroll
    for (int mi = 0; mi < 4; mi++) {
        const int r0 = bm + wm + mi * 16 + g;
        #pragma unroll
        for (int ni = 0; ni < 4; ni++) {
            const int col = bn + wn + ni * 8 + tg * 2;
            *(float2*)(Cout + (size_t)r0 * N + col) =
                make_float2(acc[mi][ni][0] * sc, acc[mi][ni][1] * sc);
            *(float2*)(Cout + (size_t)(r0 + 8) * N + col) =
                make_float2(acc[mi][ni][2] * sc, acc[mi][ni][3] * sc);
        }
    }
}

// ---------------- launch ----------------
extern "C" void kernel_launch(void* const* d_in, const int* in_sizes, int n_in,
                              void* d_out, int out_size) {
    const float* x      = (const float*)d_in[0];
    const float* basis  = (const float*)d_in[1];
    const float* qc     = (const float*)d_in[2];
    const float* kc     = (const float*)d_in[3];
    const float* vc     = (const float*)d_in[4];
    const float* oc     = (const float*)d_in[5];
    const float* decay  = (const float*)d_in[6];
    const float* oscale = (const float*)d_in[7];
    float* out = (float*)d_out;

    cvt_x_kernel<<<dim3(MT / 32, V_ / 32), 256>>>(x);
    weights_kernel<<<dim3(C_, 3), 1024>>>(basis, qc, kc, vc);
    qkv_mma_kernel<<<dim3((3 * C_) / 128, MT / 128), 256>>>();
    chunk_g_kernel<<<dim3(4, NCH, B_), 256>>>(decay);
    scan_kernel<<<128, 256>>>(decay);
    retr_kernel<<<dim3(NCH, B_), 256>>>(decay);
    oc_gemm_kernel<<<MT / 128, 256>>>(oc);
    out2_mma_kernel<<<dim3(V_ / 128, MT / 128), 256>>>(out, basis, oscale);
}

// round 8
// speedup vs baseline: 1.6136x; 1.1078x over previous
#include <cuda_runtime.h>
#include <cuda_bf16.h>
#include <math.h>
#include <stdint.h>

#define B_ 8
#define T_ 2048
#define V_ 1024
#define C_ 128
#define NB2 64   // 2*NB
#define S_ 64    // chunk size
#define NCH 32   // T_/S_
#define MT (B_ * T_)   // 16384

// ---------------- device scratch ----------------
__device__ unsigned short g_xh16[(size_t)MT * V_];   // x hi bf16, row-major [M][K]
__device__ unsigned short g_xl16[(size_t)MT * V_];   // x lo bf16
__device__ unsigned short g_wth[3 * C_ * V_];        // W^T hi bf16, [N][K]
__device__ unsigned short g_wtl[3 * C_ * V_];        // W^T lo bf16
__device__ float g_qkv[(size_t)MT * 3 * C_];         // (B*T, 384)
__device__ float g_r[(size_t)MT * C_];               // retrieved (B*T, 128)
__device__ float g_r2[(size_t)MT * NB2];             // retrieved @ oc  (B*T, 64)
__device__ float g_G[B_ * NCH * C_ * C_];            // per-chunk outer-product sums
__device__ float g_M[B_ * NCH * C_ * C_];            // chunk-boundary states

__device__ __forceinline__ float sigmoidf_(float x) { return 1.0f / (1.0f + expf(-x)); }

__device__ __forceinline__ uint32_t f2tf32(float x) {
    uint32_t r;
    asm("cvt.rna.tf32.f32 %0, %1;" : "=r"(r) : "f"(x));
    return r;
}

__device__ __forceinline__ void mma_tf32(float* c, const uint32_t* a, const uint32_t* b) {
    asm volatile(
        "mma.sync.aligned.m16n8k8.row.col.f32.tf32.tf32.f32 "
        "{%0,%1,%2,%3}, {%4,%5,%6,%7}, {%8,%9}, {%0,%1,%2,%3};"
        : "+f"(c[0]), "+f"(c[1]), "+f"(c[2]), "+f"(c[3])
        : "r"(a[0]), "r"(a[1]), "r"(a[2]), "r"(a[3]), "r"(b[0]), "r"(b[1]));
}

__device__ __forceinline__ void mma_bf16(float* c, const uint32_t* a, const uint32_t* b) {
    asm volatile(
        "mma.sync.aligned.m16n8k16.row.col.f32.bf16.bf16.f32 "
        "{%0,%1,%2,%3}, {%4,%5,%6,%7}, {%8,%9}, {%0,%1,%2,%3};"
        : "+f"(c[0]), "+f"(c[1]), "+f"(c[2]), "+f"(c[3])
        : "r"(a[0]), "r"(a[1]), "r"(a[2]), "r"(a[3]), "r"(b[0]), "r"(b[1]));
}

__device__ __forceinline__ uint32_t smem_to_u32(const void* p) {
    uint32_t a;
    asm("{ .reg .u64 t; cvta.to.shared.u64 t, %1; cvt.u32.u64 %0, t; }" : "=r"(a) : "l"(p));
    return a;
}

__device__ __forceinline__ void ldsm_x4(uint32_t* r, uint32_t addr) {
    asm volatile("ldmatrix.sync.aligned.m8n8.x4.shared.b16 {%0,%1,%2,%3}, [%4];"
                 : "=r"(r[0]), "=r"(r[1]), "=r"(r[2]), "=r"(r[3]) : "r"(addr));
}

#define CP_ASYNC16(dst, src) \
    asm volatile("cp.async.cg.shared.global [%0], [%1], 16;" :: "r"(dst), "l"(src))
#define CP_COMMIT() asm volatile("cp.async.commit_group;" ::: "memory")
#define CP_WAIT0()  asm volatile("cp.async.wait_group 0;" ::: "memory")

// ---------------- 0) convert x to bf16 hi/lo, row-major [M][K] ----------------
__global__ __launch_bounds__(256) void cvt_x_kernel(const float* __restrict__ x) {
    const size_t i = ((size_t)blockIdx.x * 256 + threadIdx.x) * 4;
    float4 v = *(const float4*)(x + i);
    float vv[4] = {v.x, v.y, v.z, v.w};
    unsigned short h[4], l[4];
    #pragma unroll
    for (int u = 0; u < 4; u++) {
        __nv_bfloat16 hb = __float2bfloat16_rn(vv[u]);
        __nv_bfloat16 lb = __float2bfloat16_rn(vv[u] - __bfloat162float(hb));
        h[u] = __bfloat16_as_ushort(hb);
        l[u] = __bfloat16_as_ushort(lb);
    }
    uint2 ph = make_uint2((uint32_t)h[0] | ((uint32_t)h[1] << 16),
                          (uint32_t)h[2] | ((uint32_t)h[3] << 16));
    uint2 pl = make_uint2((uint32_t)l[0] | ((uint32_t)l[1] << 16),
                          (uint32_t)l[2] | ((uint32_t)l[3] << 16));
    *(uint2*)(g_xh16 + i) = ph;
    *(uint2*)(g_xl16 + i) = pl;
}

// ---------------- 1) weights: basis @ coeffs^T (+ softmax over V), emit W^T bf16 hi/lo [N][K] ----------------
__global__ void weights_kernel(const float* __restrict__ basis,
                               const float* __restrict__ qc,
                               const float* __restrict__ kc,
                               const float* __restrict__ vc) {
    const int c = blockIdx.x;
    const int w = blockIdx.y;   // 0=q 1=k 2=v
    const int v = threadIdx.x;

    const float* coef = (w == 0 ? qc : (w == 1 ? kc : vc)) + c * NB2;
    __shared__ float scoef[NB2];
    __shared__ float red[32];
    __shared__ float sval;
    if (v < NB2) scoef[v] = coef[v];
    __syncthreads();

    float s = 0.f;
    const float4* brow = (const float4*)(basis + (size_t)v * NB2);
    #pragma unroll
    for (int jj = 0; jj < NB2 / 4; jj++) {
        float4 bv = brow[jj];
        s = fmaf(bv.x, scoef[4 * jj + 0], s);
        s = fmaf(bv.y, scoef[4 * jj + 1], s);
        s = fmaf(bv.z, scoef[4 * jj + 2], s);
        s = fmaf(bv.w, scoef[4 * jj + 3], s);
    }

    float m = s;
    #pragma unroll
    for (int o = 16; o; o >>= 1) m = fmaxf(m, __shfl_xor_sync(0xffffffffu, m, o));
    if ((v & 31) == 0) red[v >> 5] = m;
    __syncthreads();
    if (v < 32) {
        float t = red[v];
        #pragma unroll
        for (int o = 16; o; o >>= 1) t = fmaxf(t, __shfl_xor_sync(0xffffffffu, t, o));
        if (v == 0) sval = t;
    }
    __syncthreads();
    float e = expf(s - sval);

    float su = e;
    #pragma unroll
    for (int o = 16; o; o >>= 1) su += __shfl_xor_sync(0xffffffffu, su, o);
    if ((v & 31) == 0) red[v >> 5] = su;
    __syncthreads();
    if (v < 32) {
        float t = red[v];
        #pragma unroll
        for (int o = 16; o; o >>= 1) t += __shfl_xor_sync(0xffffffffu, t, o);
        if (v == 0) sval = t;
    }
    __syncthreads();

    const float val = e / sval;
    __nv_bfloat16 h = __float2bfloat16_rn(val);
    __nv_bfloat16 l = __float2bfloat16_rn(val - __bfloat162float(h));
    const size_t idx = (size_t)(w * C_ + c) * V_ + v;   // [N][K]
    g_wth[idx] = __bfloat16_as_ushort(h);
    g_wtl[idx] = __bfloat16_as_ushort(l);
}

// ---------------- 2) QKV GEMM via bf16x3 mma.sync + ldmatrix + cp.async ----------------
// g_qkv (16384x384) = x @ w. BM=128, BN=128, BK=32, 256 threads, warp tile 64x32.
// Smem per buffer: AH(8K) AL(8K) BH(8K) BL(8K) = 32K; 2 buffers = 64K dynamic.
// Row = 64 B (32 bf16), swizzle: physical 16B-chunk = logical ^ ((row>>1)&3).
#define QBUF 32768
__global__ __launch_bounds__(256) void qkv_mma_kernel() {
    extern __shared__ char sm[];
    const uint32_t sbase = smem_to_u32(sm);
    const int tid = threadIdx.x;
    const int warp = tid >> 5, lane = tid & 31;
    const int bm = blockIdx.y * 128;
    const int bn = blockIdx.x * 128;
    const int wm = (warp >> 2) * 64;    // 0 or 64
    const int wn = (warp & 3) * 32;     // 0,32,64,96

    // fill indexing: per it: idx = tid + it*256; row = idx>>2 (0..127), kq = idx&3
    const int frow = tid >> 2;          // 0..63 (it adds 64)
    const int fkq = tid & 3;

    // ldmatrix per-thread config
    const int arow = lane & 15;
    const int akg = lane >> 4;              // 0/1 -> k-chunk group
    const int fA = (arow >> 1) & 3;
    const int brow = ((lane >> 4) & 1) * 8 + (lane & 7);
    const int bkg = (lane >> 3) & 1;
    const int fB = (brow >> 1) & 3;

    float acc[4][4][4] = {};

    // ---- prologue: fill buffer 0 (chunk 0) ----
    #pragma unroll
    for (int it = 0; it < 2; it++) {
        const int row = frow + it * 64;
        const uint32_t dst = sbase + row * 64 + ((fkq ^ ((row >> 1) & 3)) * 16);
        CP_ASYNC16(dst,         g_xh16 + (size_t)(bm + row) * V_ + fkq * 8);
        CP_ASYNC16(dst + 8192,  g_xl16 + (size_t)(bm + row) * V_ + fkq * 8);
        CP_ASYNC16(dst + 16384, g_wth + (size_t)(bn + row) * V_ + fkq * 8);
        CP_ASYNC16(dst + 24576, g_wtl + (size_t)(bn + row) * V_ + fkq * 8);
    }
    CP_COMMIT();
    CP_WAIT0();
    __syncthreads();

    int buf = 0;
    for (int ch = 0; ch < 32; ch++) {
        const bool has_next = (ch + 1 < 32);
        if (has_next) {
            const int c0 = (ch + 1) * 32;
            const uint32_t nb = sbase + (buf ^ 1) * QBUF;
            #pragma unroll
            for (int it = 0; it < 2; it++) {
                const int row = frow + it * 64;
                const uint32_t dst = nb + row * 64 + ((fkq ^ ((row >> 1) & 3)) * 16);
                CP_ASYNC16(dst,         g_xh16 + (size_t)(bm + row) * V_ + c0 + fkq * 8);
                CP_ASYNC16(dst + 8192,  g_xl16 + (size_t)(bm + row) * V_ + c0 + fkq * 8);
                CP_ASYNC16(dst + 16384, g_wth + (size_t)(bn + row) * V_ + c0 + fkq * 8);
                CP_ASYNC16(dst + 24576, g_wtl + (size_t)(bn + row) * V_ + c0 + fkq * 8);
            }
            CP_COMMIT();
        }

        const uint32_t cb = sbase + buf * QBUF;
        #pragma unroll
        for (int ks = 0; ks < 2; ks++) {
            // A fragments (hi/lo) for 4 mi blocks
            uint32_t a_h[4][4], a_l[4][4];
            const uint32_t achunk = (uint32_t)(((ks * 2 + akg) ^ fA) * 16);
            #pragma unroll
            for (int mi = 0; mi < 4; mi++) {
                const uint32_t aaddr = cb + (uint32_t)((wm + mi * 16 + arow) * 64) + achunk;
                ldsm_x4(a_h[mi], aaddr);
                ldsm_x4(a_l[mi], aaddr + 8192);
            }
            // B fragments (hi/lo) for 4 ni blocks (2 per ldmatrix.x4)
            uint32_t b_h[4][2], b_l[4][2];
            const uint32_t bchunk = (uint32_t)(((ks * 2 + bkg) ^ fB) * 16);
            #pragma unroll
            for (int nip = 0; nip < 2; nip++) {
                const uint32_t baddr = cb + 16384 +
                    (uint32_t)((wn + nip * 16 + brow) * 64) + bchunk;
                uint32_t rh[4], rl[4];
                ldsm_x4(rh, baddr);
                ldsm_x4(rl, baddr + 8192);
                b_h[nip * 2 + 0][0] = rh[0]; b_h[nip * 2 + 0][1] = rh[1];
                b_h[nip * 2 + 1][0] = rh[2]; b_h[nip * 2 + 1][1] = rh[3];
                b_l[nip * 2 + 0][0] = rl[0]; b_l[nip * 2 + 0][1] = rl[1];
                b_l[nip * 2 + 1][0] = rl[2]; b_l[nip * 2 + 1][1] = rl[3];
            }
            #pragma unroll
            for (int mi = 0; mi < 4; mi++)
                #pragma unroll
                for (int ni = 0; ni < 4; ni++) {
                    mma_bf16(acc[mi][ni], a_l[mi], b_h[ni]);
                    mma_bf16(acc[mi][ni], a_h[mi], b_l[ni]);
                    mma_bf16(acc[mi][ni], a_h[mi], b_h[ni]);
                }
        }

        if (has_next) CP_WAIT0();
        __syncthreads();
        buf ^= 1;
    }

    // ---- epilogue ----
    const int g = lane >> 2, tg = lane & 3;
    #pragma unroll
    for (int mi = 0; mi < 4; mi++) {
        const int r0 = bm + wm + mi * 16 + g;
        #pragma unroll
        for (int ni = 0; ni < 4; ni++) {
            const int col = bn + wn + ni * 8 + tg * 2;
            *(float2*)(g_qkv + (size_t)r0 * (3 * C_) + col) =
                make_float2(acc[mi][ni][0], acc[mi][ni][1]);
            *(float2*)(g_qkv + (size_t)(r0 + 8) * (3 * C_) + col) =
                make_float2(acc[mi][ni][2], acc[mi][ni][3]);
        }
    }
}

// ---------------- 3a) per-chunk outer-product sums ----------------
__global__ __launch_bounds__(256) void chunk_g_kernel(const float* __restrict__ decay_ptr) {
    const int cg = blockIdx.x;
    const int j  = blockIdx.y;
    const int b  = blockIdx.z;
    const float dec = sigmoidf_(decay_ptr[0]);
    const float l2d = log2f(dec);

    __shared__ float Ks[32][128];
    __shared__ float Vs[32][32];

    const int tid = threadIdx.x;
    const int trow = tid >> 3;
    const int tcol = tid & 7;
    const int r  = tid >> 3;
    const int q8 = tid & 7;

    float acc[4][4] = {};
    const float* base = g_qkv + ((size_t)b * T_ + (size_t)j * S_) * (3 * C_);

    #pragma unroll
    for (int i0 = 0; i0 < S_; i0 += 32) {
        const float sc = exp2f((float)(S_ - 1 - (i0 + r)) * l2d);
        const float* krow = base + (size_t)(i0 + r) * (3 * C_) + C_;
        #pragma unroll
        for (int u = 0; u < 4; u++) {
            float4 kv = *(const float4*)(krow + (q8 + u * 8) * 4);
            Ks[r][(q8 + u * 8) * 4 + 0] = kv.x * sc;
            Ks[r][(q8 + u * 8) * 4 + 1] = kv.y * sc;
            Ks[r][(q8 + u * 8) * 4 + 2] = kv.z * sc;
            Ks[r][(q8 + u * 8) * 4 + 3] = kv.w * sc;
        }
        *(float4*)&Vs[r][q8 * 4] =
            *(const float4*)(base + (size_t)(i0 + r) * (3 * C_) + 2 * C_ + cg * 32 + q8 * 4);
        __syncthreads();
        #pragma unroll
        for (int ii = 0; ii < 32; ii++) {
            float4 a4 = *(const float4*)&Ks[ii][trow * 4];
            float4 b4 = *(const float4*)&Vs[ii][tcol * 4];
            float ar[4] = {a4.x, a4.y, a4.z, a4.w};
            float br[4] = {b4.x, b4.y, b4.z, b4.w};
            #pragma unroll
            for (int m = 0; m < 4; m++)
                #pragma unroll
                for (int n = 0; n < 4; n++)
                    acc[m][n] = fmaf(ar[m], br[n], acc[m][n]);
        }
        __syncthreads();
    }

    float* gout = g_G + ((size_t)(b * NCH + j) * C_ * C_) + cg * 32;
    #pragma unroll
    for (int m = 0; m < 4; m++)
        *(float4*)(gout + (size_t)(trow * 4 + m) * C_ + tcol * 4) =
            make_float4(acc[m][0], acc[m][1], acc[m][2], acc[m][3]);
}

// ---------------- 3b) scan with batched prefetch ----------------
__global__ void scan_kernel(const float* __restrict__ decay_ptr) {
    const int idx = blockIdx.x * blockDim.x + threadIdx.x;
    const int b = idx >> 12;
    const int e4 = idx & 4095;
    const float dec = sigmoidf_(decay_ptr[0]);
    const float dS = exp2f((float)S_ * log2f(dec));

    const float4* G = (const float4*)(g_G + (size_t)b * NCH * C_ * C_) + e4;
    float4* M = (float4*)(g_M + (size_t)b * NCH * C_ * C_) + e4;

    float4 m = make_float4(0.f, 0.f, 0.f, 0.f);
    #pragma unroll
    for (int jb = 0; jb < NCH; jb += 8) {
        float4 buf[8];
        #pragma unroll
        for (int u = 0; u < 8; u++) buf[u] = G[(size_t)(jb + u) * 4096];
        #pragma unroll
        for (int u = 0; u < 8; u++) {
            M[(size_t)(jb + u) * 4096] = m;
            m.x = fmaf(dS, m.x, buf[u].x);
            m.y = fmaf(dS, m.y, buf[u].y);
            m.z = fmaf(dS, m.z, buf[u].z);
            m.w = fmaf(dS, m.w, buf[u].w);
        }
    }
}

// ---------------- 3c) retrieval per chunk ----------------
__global__ __launch_bounds__(256) void retr_kernel(const float* __restrict__ decay_ptr) {
    const int j = blockIdx.x;
    const int b = blockIdx.y;
    const float dec = sigmoidf_(decay_ptr[0]);
    const float l2d = log2f(dec);

    __shared__ float Qs[32][64];
    __shared__ float Ks2[32][64];
    __shared__ float As[64][64];
    __shared__ float Vs[32][128];

    const int tid = threadIdx.x;
    const float* base = g_qkv + ((size_t)b * T_ + (size_t)j * S_) * (3 * C_);

    {
        const int ti = tid >> 4;
        const int ts = tid & 15;
        const int li = tid >> 2;
        const int lp = tid & 3;

        float acc[4][4] = {};
        for (int c0 = 0; c0 < C_; c0 += 32) {
            #pragma unroll
            for (int u = 0; u < 2; u++) {
                int c = lp * 8 + u * 4;
                float4 qv = *(const float4*)(base + (size_t)li * (3 * C_) + c0 + c);
                Qs[c + 0][li] = qv.x; Qs[c + 1][li] = qv.y;
                Qs[c + 2][li] = qv.z; Qs[c + 3][li] = qv.w;
                float4 kv = *(const float4*)(base + (size_t)li * (3 * C_) + C_ + c0 + c);
                Ks2[c + 0][li] = kv.x; Ks2[c + 1][li] = kv.y;
                Ks2[c + 2][li] = kv.z; Ks2[c + 3][li] = kv.w;
            }
            __syncthreads();
            #pragma unroll
            for (int cc = 0; cc < 32; cc++) {
                float4 a4 = *(const float4*)&Qs[cc][ti * 4];
                float4 b4 = *(const float4*)&Ks2[cc][ts * 4];
                float ar[4] = {a4.x, a4.y, a4.z, a4.w};
                float br[4] = {b4.x, b4.y, b4.z, b4.w};
                #pragma unroll
                for (int m = 0; m < 4; m++)
                    #pragma unroll
                    for (int n = 0; n < 4; n++)
                        acc[m][n] = fmaf(ar[m], br[n], acc[m][n]);
            }
            __syncthreads();
        }
        #pragma unroll
        for (int m = 0; m < 4; m++) {
            const int i = ti * 4 + m;
            #pragma unroll
            for (int n = 0; n < 4; n++) {
                const int s = ts * 4 + n;
                float v = 0.f;
                if (s < i) v = acc[m][n] * exp2f((float)(i - 1 - s) * l2d);
                As[s][i] = v;
            }
        }
    }
    __syncthreads();

    const int ti2 = tid >> 4;
    const int td  = tid & 15;
    const int lr  = tid >> 3;
    const int lq  = tid & 7;

    float accA[4][8] = {};
    float accM[4][8] = {};

    for (int s0 = 0; s0 < S_; s0 += 32) {
        #pragma unroll
        for (int u = 0; u < 4; u++) {
            int c4 = lq + u * 8;
            *(float4*)&Vs[lr][c4 * 4] =
                *(const float4*)(base + (size_t)(s0 + lr) * (3 * C_) + 2 * C_ + c4 * 4);
        }
        __syncthreads();
        #pragma unroll
        for (int ss = 0; ss < 32; ss++) {
            float4 a4 = *(const float4*)&As[s0 + ss][ti2 * 4];
            float4 b0 = *(const float4*)&Vs[ss][td * 8];
            float4 b1 = *(const float4*)&Vs[ss][td * 8 + 4];
            float ar[4] = {a4.x, a4.y, a4.z, a4.w};
            float br[8] = {b0.x, b0.y, b0.z, b0.w, b1.x, b1.y, b1.z, b1.w};
            #pragma unroll
            for (int m = 0; m < 4; m++)
                #pragma unroll
                for (int n = 0; n < 8; n++)
                    accA[m][n] = fmaf(ar[m], br[n], accA[m][n]);
        }
        __syncthreads();
    }

    const float* Mbase = g_M + (size_t)(b * NCH + j) * C_ * C_;
    {
        const int li = tid >> 2;
        const int lp = tid & 3;
        for (int c0 = 0; c0 < C_; c0 += 32) {
            #pragma unroll
            for (int u = 0; u < 2; u++) {
                int c = lp * 8 + u * 4;
                float4 qv = *(const float4*)(base + (size_t)li * (3 * C_) + c0 + c);
                Qs[c + 0][li] = qv.x; Qs[c + 1][li] = qv.y;
                Qs[c + 2][li] = qv.z; Qs[c + 3][li] = qv.w;
            }
            #pragma unroll
            for (int u = 0; u < 4; u++) {
                int c4 = lq + u * 8;
                *(float4*)&Vs[lr][c4 * 4] =
                    *(const float4*)(Mbase + (size_t)(c0 + lr) * C_ + c4 * 4);
            }
            __syncthreads();
            #pragma unroll
            for (int cc = 0; cc < 32; cc++) {
                float4 a4 = *(const float4*)&Qs[cc][ti2 * 4];
                float4 b0 = *(const float4*)&Vs[cc][td * 8];
                float4 b1 = *(const float4*)&Vs[cc][td * 8 + 4];
                float ar[4] = {a4.x, a4.y, a4.z, a4.w};
                float br[8] = {b0.x, b0.y, b0.z, b0.w, b1.x, b1.y, b1.z, b1.w};
                #pragma unroll
                for (int m = 0; m < 4; m++)
                    #pragma unroll
                    for (int n = 0; n < 8; n++)
                        accM[m][n] = fmaf(ar[m], br[n], accM[m][n]);
            }
            __syncthreads();
        }
    }

    float* rout = g_r + ((size_t)b * T_ + (size_t)j * S_) * C_;
    #pragma unroll
    for (int m = 0; m < 4; m++) {
        const int i = ti2 * 4 + m;
        const float di = exp2f((float)i * l2d);
        float o[8];
        #pragma unroll
        for (int n = 0; n < 8; n++) o[n] = fmaf(di, accM[m][n], accA[m][n]);
        *(float4*)(rout + (size_t)i * C_ + td * 8)     = make_float4(o[0], o[1], o[2], o[3]);
        *(float4*)(rout + (size_t)i * C_ + td * 8 + 4) = make_float4(o[4], o[5], o[6], o[7]);
    }
}

// ---------------- 4a) r2 = g_r (16384x128) @ oc (128x64) ----------------
__global__ __launch_bounds__(256) void oc_gemm_kernel(const float* __restrict__ oc) {
    constexpr int BK = 16;
    __shared__ float As[BK][C_];
    __shared__ float Bs[BK][NB2];

    const int tid = threadIdx.x;
    const int bm = blockIdx.x * 128;
    const int trow = tid >> 4;
    const int tcol = tid & 15;

    float acc[8][4] = {};

    for (int k0 = 0; k0 < C_; k0 += BK) {
        #pragma unroll
        for (int t = 0; t < 2; t++) {
            int idx = tid + t * 256;
            int m = idx >> 2, k4 = (idx & 3) * 4;
            float4 a4 = *(const float4*)(g_r + (size_t)(bm + m) * C_ + k0 + k4);
            As[k4 + 0][m] = a4.x; As[k4 + 1][m] = a4.y;
            As[k4 + 2][m] = a4.z; As[k4 + 3][m] = a4.w;
        }
        {
            int k = tid >> 4, n4 = (tid & 15) * 4;
            *(float4*)&Bs[k][n4] = *(const float4*)(oc + (size_t)(k0 + k) * NB2 + n4);
        }
        __syncthreads();
        #pragma unroll
        for (int kk = 0; kk < BK; kk++) {
            float ar[8], br[4];
            *(float4*)&ar[0] = *(const float4*)&As[kk][trow * 8];
            *(float4*)&ar[4] = *(const float4*)&As[kk][trow * 8 + 4];
            *(float4*)&br[0] = *(const float4*)&Bs[kk][tcol * 4];
            #pragma unroll
            for (int i = 0; i < 8; i++)
                #pragma unroll
                for (int jn = 0; jn < 4; jn++)
                    acc[i][jn] = fmaf(ar[i], br[jn], acc[i][jn]);
        }
        __syncthreads();
    }
    #pragma unroll
    for (int i = 0; i < 8; i++)
        *(float4*)(g_r2 + (size_t)(bm + trow * 8 + i) * NB2 + tcol * 4) =
            make_float4(acc[i][0], acc[i][1], acc[i][2], acc[i][3]);
}

// ---------------- 4b) out = g_r2 (16384x64) @ basis^T (64x1024) * scale, tf32 MMA ----------------
#define QP2 132
__global__ __launch_bounds__(256) void out2_mma_kernel(float* __restrict__ Cout,
                                                       const float* __restrict__ basis,
                                                       const float* __restrict__ scale_ptr) {
    constexpr int K = NB2;   // 64
    constexpr int N = V_;    // 1024
    __shared__ uint32_t Ah[2][8][QP2], Al[2][8][QP2];
    __shared__ uint32_t Bh[2][8][QP2], Bl[2][8][QP2];

    const int tid = threadIdx.x;
    const int bm = blockIdx.y * 128;
    const int bn = blockIdx.x * 128;
    const int warp = tid >> 5, lane = tid & 31;
    const int g = lane >> 2, tg = lane & 3;
    const int wm = (warp >> 2) * 64;
    const int wn = (warp & 3) * 32;

    const int am = tid >> 1, ak = (tid & 1) * 4;

    float acc[4][4][4] = {};
    float4 ra, rb;

    ra = *(const float4*)(g_r2 + (size_t)(bm + am) * K + ak);
    rb = *(const float4*)(basis + (size_t)(bn + am) * K + ak);
    {
        float av[4] = {ra.x, ra.y, ra.z, ra.w};
        float bv[4] = {rb.x, rb.y, rb.z, rb.w};
        #pragma unroll
        for (int j2 = 0; j2 < 4; j2++) {
            uint32_t h = f2tf32(av[j2]);
            Ah[0][ak + j2][am] = h;
            Al[0][ak + j2][am] = f2tf32(av[j2] - __uint_as_float(h));
            uint32_t hb = f2tf32(bv[j2]);
            Bh[0][ak + j2][am] = hb;
            Bl[0][ak + j2][am] = f2tf32(bv[j2] - __uint_as_float(hb));
        }
    }
    __syncthreads();

    int buf = 0;
    for (int k0 = 0; k0 < K; k0 += 8) {
        const bool has_next = (k0 + 8 < K);
        if (has_next) {
            ra = *(const float4*)(g_r2 + (size_t)(bm + am) * K + k0 + 8 + ak);
            rb = *(const float4*)(basis + (size_t)(bn + am) * K + k0 + 8 + ak);
        }

        uint32_t bh[4][2], bl[4][2];
        #pragma unroll
        for (int ni = 0; ni < 4; ni++) {
            const int nc = wn + ni * 8 + g;
            bh[ni][0] = Bh[buf][tg][nc];
            bh[ni][1] = Bh[buf][tg + 4][nc];
            bl[ni][0] = Bl[buf][tg][nc];
            bl[ni][1] = Bl[buf][tg + 4][nc];
        }
        #pragma unroll
        for (int mi = 0; mi < 4; mi++) {
            const int mr = wm + mi * 16 + g;
            uint32_t ah[4], al[4];
            ah[0] = Ah[buf][tg][mr];     ah[1] = Ah[buf][tg][mr + 8];
            ah[2] = Ah[buf][tg + 4][mr]; ah[3] = Ah[buf][tg + 4][mr + 8];
            al[0] = Al[buf][tg][mr];     al[1] = Al[buf][tg][mr + 8];
            al[2] = Al[buf][tg + 4][mr]; al[3] = Al[buf][tg + 4][mr + 8];
            #pragma unroll
            for (int ni = 0; ni < 4; ni++) {
                mma_tf32(acc[mi][ni], al, bh[ni]);
                mma_tf32(acc[mi][ni], ah, bl[ni]);
                mma_tf32(acc[mi][ni], ah, bh[ni]);
            }
        }

        if (has_next) {
            float av[4] = {ra.x, ra.y, ra.z, ra.w};
            float bv[4] = {rb.x, rb.y, rb.z, rb.w};
            #pragma unroll
            for (int j2 = 0; j2 < 4; j2++) {
                uint32_t h = f2tf32(av[j2]);
                Ah[buf ^ 1][ak + j2][am] = h;
                Al[buf ^ 1][ak + j2][am] = f2tf32(av[j2] - __uint_as_float(h));
                uint32_t hb = f2tf32(bv[j2]);
                Bh[buf ^ 1][ak + j2][am] = hb;
                Bl[buf ^ 1][ak + j2][am] = f2tf32(bv[j2] - __uint_as_float(hb));
            }
        }
        __syncthreads();
        buf ^= 1;
    }

    const float sc = *scale_ptr;
    #pragma unroll
    for (int mi = 0; mi < 4; mi++) {
        const int r0 = bm + wm + mi * 16 + g;
        #pragma unroll
        for (int ni = 0; ni < 4; ni++) {
            const int col = bn + wn + ni * 8 + tg * 2;
            *(float2*)(Cout + (size_t)r0 * N + col) =
                make_float2(acc[mi][ni][0] * sc, acc[mi][ni][1] * sc);
            *(float2*)(Cout + (size_t)(r0 + 8) * N + col) =
                make_float2(acc[mi][ni][2] * sc, acc[mi][ni][3] * sc);
        }
    }
}

// ---------------- launch ----------------
extern "C" void kernel_launch(void* const* d_in, const int* in_sizes, int n_in,
                              void* d_out, int out_size) {
    const float* x      = (const float*)d_in[0];
    const float* basis  = (const float*)d_in[1];
    const float* qc     = (const float*)d_in[2];
    const float* kc     = (const float*)d_in[3];
    const float* vc     = (const float*)d_in[4];
    const float* oc     = (const float*)d_in[5];
    const float* decay  = (const float*)d_in[6];
    const float* oscale = (const float*)d_in[7];
    float* out = (float*)d_out;

    cudaFuncSetAttribute(qkv_mma_kernel, cudaFuncAttributeMaxDynamicSharedMemorySize, 2 * QBUF);

    cvt_x_kernel<<<(MT * V_) / 1024, 256>>>(x);
    weights_kernel<<<dim3(C_, 3), 1024>>>(basis, qc, kc, vc);
    qkv_mma_kernel<<<dim3(3, MT / 128), 256, 2 * QBUF>>>();
    chunk_g_kernel<<<dim3(4, NCH, B_), 256>>>(decay);
    scan_kernel<<<128, 256>>>(decay);
    retr_kernel<<<dim3(NCH, B_), 256>>>(decay);
    oc_gemm_kernel<<<MT / 128, 256>>>(oc);
    out2_mma_kernel<<<dim3(V_ / 128, MT / 128), 256>>>(out, basis, oscale);
}

// round 9
// speedup vs baseline: 1.8615x; 1.1536x over previous
#include <cuda_runtime.h>
#include <cuda_bf16.h>
#include <math.h>
#include <stdint.h>

#define B_ 8
#define T_ 2048
#define V_ 1024
#define C_ 128
#define NB2 64   // 2*NB
#define S_ 64    // chunk size
#define NCH 32   // T_/S_
#define MT (B_ * T_)   // 16384

// ---------------- device scratch ----------------
__device__ unsigned short g_xh16[(size_t)MT * V_];   // x hi bf16, row-major [M][K]
__device__ unsigned short g_xl16[(size_t)MT * V_];   // x lo bf16
__device__ unsigned short g_wth[3 * C_ * V_];        // W^T hi bf16, [N][K]
__device__ unsigned short g_wtl[3 * C_ * V_];        // W^T lo bf16
__device__ float g_logits[3 * C_ * V_];              // logits [N][V]
__device__ unsigned short g_bh[V_ * NB2];            // basis hi bf16 [N][K]
__device__ unsigned short g_bl[V_ * NB2];            // basis lo bf16
__device__ unsigned short g_r2h[(size_t)MT * NB2];   // r2 hi bf16 [M][64]
__device__ unsigned short g_r2l[(size_t)MT * NB2];   // r2 lo bf16
__device__ float g_qkv[(size_t)MT * 3 * C_];         // (B*T, 384)
__device__ float g_r[(size_t)MT * C_];               // retrieved (B*T, 128)
__device__ float g_G[B_ * NCH * C_ * C_];            // per-chunk outer-product sums
__device__ float g_M[B_ * NCH * C_ * C_];            // chunk-boundary states

__device__ __forceinline__ float sigmoidf_(float x) { return 1.0f / (1.0f + expf(-x)); }

__device__ __forceinline__ void mma_bf16(float* c, const uint32_t* a, const uint32_t* b) {
    asm volatile(
        "mma.sync.aligned.m16n8k16.row.col.f32.bf16.bf16.f32 "
        "{%0,%1,%2,%3}, {%4,%5,%6,%7}, {%8,%9}, {%0,%1,%2,%3};"
        : "+f"(c[0]), "+f"(c[1]), "+f"(c[2]), "+f"(c[3])
        : "r"(a[0]), "r"(a[1]), "r"(a[2]), "r"(a[3]), "r"(b[0]), "r"(b[1]));
}

__device__ __forceinline__ uint32_t smem_to_u32(const void* p) {
    uint32_t a;
    asm("{ .reg .u64 t; cvta.to.shared.u64 t, %1; cvt.u32.u64 %0, t; }" : "=r"(a) : "l"(p));
    return a;
}

__device__ __forceinline__ void ldsm_x4(uint32_t* r, uint32_t addr) {
    asm volatile("ldmatrix.sync.aligned.m8n8.x4.shared.b16 {%0,%1,%2,%3}, [%4];"
                 : "=r"(r[0]), "=r"(r[1]), "=r"(r[2]), "=r"(r[3]) : "r"(addr));
}

#define CP_ASYNC16(dst, src) \
    asm volatile("cp.async.cg.shared.global [%0], [%1], 16;" :: "r"(dst), "l"(src))
#define CP_COMMIT() asm volatile("cp.async.commit_group;" ::: "memory")
#define CP_WAIT0()  asm volatile("cp.async.wait_group 0;" ::: "memory")
#define CP_WAIT1()  asm volatile("cp.async.wait_group 1;" ::: "memory")

// ---------------- 0a) convert x to bf16 hi/lo, row-major [M][K] ----------------
__global__ __launch_bounds__(256) void cvt_x_kernel(const float* __restrict__ x) {
    const size_t i = ((size_t)blockIdx.x * 256 + threadIdx.x) * 4;
    float4 v = *(const float4*)(x + i);
    float vv[4] = {v.x, v.y, v.z, v.w};
    unsigned short h[4], l[4];
    #pragma unroll
    for (int u = 0; u < 4; u++) {
        __nv_bfloat16 hb = __float2bfloat16_rn(vv[u]);
        __nv_bfloat16 lb = __float2bfloat16_rn(vv[u] - __bfloat162float(hb));
        h[u] = __bfloat16_as_ushort(hb);
        l[u] = __bfloat16_as_ushort(lb);
    }
    *(uint2*)(g_xh16 + i) = make_uint2((uint32_t)h[0] | ((uint32_t)h[1] << 16),
                                       (uint32_t)h[2] | ((uint32_t)h[3] << 16));
    *(uint2*)(g_xl16 + i) = make_uint2((uint32_t)l[0] | ((uint32_t)l[1] << 16),
                                       (uint32_t)l[2] | ((uint32_t)l[3] << 16));
}

// ---------------- 0b) convert basis to bf16 hi/lo [N][K] ----------------
__global__ __launch_bounds__(256) void cvt_basis_kernel(const float* __restrict__ basis) {
    const size_t i = ((size_t)blockIdx.x * 256 + threadIdx.x) * 4;
    float4 v = *(const float4*)(basis + i);
    float vv[4] = {v.x, v.y, v.z, v.w};
    unsigned short h[4], l[4];
    #pragma unroll
    for (int u = 0; u < 4; u++) {
        __nv_bfloat16 hb = __float2bfloat16_rn(vv[u]);
        __nv_bfloat16 lb = __float2bfloat16_rn(vv[u] - __bfloat162float(hb));
        h[u] = __bfloat16_as_ushort(hb);
        l[u] = __bfloat16_as_ushort(lb);
    }
    *(uint2*)(g_bh + i) = make_uint2((uint32_t)h[0] | ((uint32_t)h[1] << 16),
                                     (uint32_t)h[2] | ((uint32_t)h[3] << 16));
    *(uint2*)(g_bl + i) = make_uint2((uint32_t)l[0] | ((uint32_t)l[1] << 16),
                                     (uint32_t)l[2] | ((uint32_t)l[3] << 16));
}

// ---------------- 1a) logits = coeffs @ basis^T, written [N][V] ----------------
// grid (3, 8): w, vblock. block 256. Tile 128c x 128v, K=64.
__global__ __launch_bounds__(256) void logits_kernel(const float* __restrict__ basis,
                                                     const float* __restrict__ qc,
                                                     const float* __restrict__ kc,
                                                     const float* __restrict__ vc) {
    const int w = blockIdx.x;
    const int vb = blockIdx.y;
    const float* coef = (w == 0 ? qc : (w == 1 ? kc : vc));

    __shared__ float Cs[NB2][C_ + 4];   // [k][c]
    __shared__ float Bs[NB2][C_ + 4];   // [k][v]

    const int tid = threadIdx.x;
    const int lr = tid >> 1;            // 0..127 (source row)
    const int lk = (tid & 1) * 32;      // 0 or 32 (k offset, 8 floats x4)

    // load transposed
    #pragma unroll
    for (int u = 0; u < 8; u++) {
        const int k = lk + u * 4;
        float4 cv = *(const float4*)(coef + (size_t)lr * NB2 + k);
        Cs[k + 0][lr] = cv.x; Cs[k + 1][lr] = cv.y;
        Cs[k + 2][lr] = cv.z; Cs[k + 3][lr] = cv.w;
        float4 bv = *(const float4*)(basis + (size_t)(vb * 128 + lr) * NB2 + k);
        Bs[k + 0][lr] = bv.x; Bs[k + 1][lr] = bv.y;
        Bs[k + 2][lr] = bv.z; Bs[k + 3][lr] = bv.w;
    }
    __syncthreads();

    const int trow = tid >> 4;   // c rows trow*8
    const int tcol = tid & 15;   // v cols tcol*8
    float acc[8][8] = {};
    #pragma unroll
    for (int kk = 0; kk < NB2; kk++) {
        float ar[8], br[8];
        *(float4*)&ar[0] = *(const float4*)&Cs[kk][trow * 8];
        *(float4*)&ar[4] = *(const float4*)&Cs[kk][trow * 8 + 4];
        *(float4*)&br[0] = *(const float4*)&Bs[kk][tcol * 8];
        *(float4*)&br[4] = *(const float4*)&Bs[kk][tcol * 8 + 4];
        #pragma unroll
        for (int i = 0; i < 8; i++)
            #pragma unroll
            for (int jn = 0; jn < 8; jn++)
                acc[i][jn] = fmaf(ar[i], br[jn], acc[i][jn]);
    }
    #pragma unroll
    for (int i = 0; i < 8; i++) {
        float* lrow = g_logits + (size_t)(w * C_ + trow * 8 + i) * V_ + vb * 128 + tcol * 8;
        *(float4*)(lrow)     = make_float4(acc[i][0], acc[i][1], acc[i][2], acc[i][3]);
        *(float4*)(lrow + 4) = make_float4(acc[i][4], acc[i][5], acc[i][6], acc[i][7]);
    }
}

// ---------------- 1b) column softmax over V, emit W^T bf16 hi/lo [N][K] ----------------
__global__ void softmax_w_kernel() {
    const int n = blockIdx.x;    // 0..383
    const int v = threadIdx.x;   // 0..1023
    __shared__ float red[32];
    __shared__ float sval;

    float s = g_logits[(size_t)n * V_ + v];

    float m = s;
    #pragma unroll
    for (int o = 16; o; o >>= 1) m = fmaxf(m, __shfl_xor_sync(0xffffffffu, m, o));
    if ((v & 31) == 0) red[v >> 5] = m;
    __syncthreads();
    if (v < 32) {
        float t = red[v];
        #pragma unroll
        for (int o = 16; o; o >>= 1) t = fmaxf(t, __shfl_xor_sync(0xffffffffu, t, o));
        if (v == 0) sval = t;
    }
    __syncthreads();
    float e = expf(s - sval);

    float su = e;
    #pragma unroll
    for (int o = 16; o; o >>= 1) su += __shfl_xor_sync(0xffffffffu, su, o);
    if ((v & 31) == 0) red[v >> 5] = su;
    __syncthreads();
    if (v < 32) {
        float t = red[v];
        #pragma unroll
        for (int o = 16; o; o >>= 1) t += __shfl_xor_sync(0xffffffffu, t, o);
        if (v == 0) sval = t;
    }
    __syncthreads();

    const float val = e / sval;
    __nv_bfloat16 h = __float2bfloat16_rn(val);
    __nv_bfloat16 l = __float2bfloat16_rn(val - __bfloat162float(h));
    g_wth[(size_t)n * V_ + v] = __bfloat16_as_ushort(h);
    g_wtl[(size_t)n * V_ + v] = __bfloat16_as_ushort(l);
}

// ---------------- 2) QKV GEMM: bf16x3 mma.sync + ldmatrix + 3-stage cp.async ----------------
#define QBUF 32768
__global__ __launch_bounds__(256) void qkv_mma_kernel() {
    extern __shared__ char sm[];
    const uint32_t sbase = smem_to_u32(sm);
    const int tid = threadIdx.x;
    const int warp = tid >> 5, lane = tid & 31;
    const int bm = blockIdx.y * 128;
    const int bn = blockIdx.x * 128;
    const int wm = (warp >> 2) * 64;
    const int wn = (warp & 3) * 32;

    const int frow = tid >> 2;
    const int fkq = tid & 3;

    const int arow = lane & 15;
    const int akg = lane >> 4;
    const int fA = (arow >> 1) & 3;
    const int brow = ((lane >> 4) & 1) * 8 + (lane & 7);
    const int bkg = (lane >> 3) & 1;
    const int fB = (brow >> 1) & 3;

    float acc[4][4][4] = {};

    // fill helper (macro-free inline)
    auto fill = [&](int stage, int c0) {
        const uint32_t nb = sbase + stage * QBUF;
        #pragma unroll
        for (int it = 0; it < 2; it++) {
            const int row = frow + it * 64;
            const uint32_t dst = nb + row * 64 + ((fkq ^ ((row >> 1) & 3)) * 16);
            CP_ASYNC16(dst,         g_xh16 + (size_t)(bm + row) * V_ + c0 + fkq * 8);
            CP_ASYNC16(dst + 8192,  g_xl16 + (size_t)(bm + row) * V_ + c0 + fkq * 8);
            CP_ASYNC16(dst + 16384, g_wth + (size_t)(bn + row) * V_ + c0 + fkq * 8);
            CP_ASYNC16(dst + 24576, g_wtl + (size_t)(bn + row) * V_ + c0 + fkq * 8);
        }
    };

    fill(0, 0);  CP_COMMIT();
    fill(1, 32); CP_COMMIT();

    for (int ch = 0; ch < 32; ch++) {
        CP_WAIT1();
        __syncthreads();

        const uint32_t cb = sbase + (ch % 3) * QBUF;
        #pragma unroll
        for (int ks = 0; ks < 2; ks++) {
            uint32_t a_h[4][4], a_l[4][4];
            const uint32_t achunk = (uint32_t)(((ks * 2 + akg) ^ fA) * 16);
            #pragma unroll
            for (int mi = 0; mi < 4; mi++) {
                const uint32_t aaddr = cb + (uint32_t)((wm + mi * 16 + arow) * 64) + achunk;
                ldsm_x4(a_h[mi], aaddr);
                ldsm_x4(a_l[mi], aaddr + 8192);
            }
            uint32_t b_h[4][2], b_l[4][2];
            const uint32_t bchunk = (uint32_t)(((ks * 2 + bkg) ^ fB) * 16);
            #pragma unroll
            for (int nip = 0; nip < 2; nip++) {
                const uint32_t baddr = cb + 16384 +
                    (uint32_t)((wn + nip * 16 + brow) * 64) + bchunk;
                uint32_t rh[4], rl[4];
                ldsm_x4(rh, baddr);
                ldsm_x4(rl, baddr + 8192);
                b_h[nip * 2 + 0][0] = rh[0]; b_h[nip * 2 + 0][1] = rh[1];
                b_h[nip * 2 + 1][0] = rh[2]; b_h[nip * 2 + 1][1] = rh[3];
                b_l[nip * 2 + 0][0] = rl[0]; b_l[nip * 2 + 0][1] = rl[1];
                b_l[nip * 2 + 1][0] = rl[2]; b_l[nip * 2 + 1][1] = rl[3];
            }
            #pragma unroll
            for (int mi = 0; mi < 4; mi++)
                #pragma unroll
                for (int ni = 0; ni < 4; ni++) {
                    mma_bf16(acc[mi][ni], a_l[mi], b_h[ni]);
                    mma_bf16(acc[mi][ni], a_h[mi], b_l[ni]);
                    mma_bf16(acc[mi][ni], a_h[mi], b_h[ni]);
                }
        }

        __syncthreads();
        if (ch + 2 < 32) fill((ch + 2) % 3, (ch + 2) * 32);
        CP_COMMIT();   // empty group when no fill keeps wait_group invariant
    }

    const int g = lane >> 2, tg = lane & 3;
    #pragma unroll
    for (int mi = 0; mi < 4; mi++) {
        const int r0 = bm + wm + mi * 16 + g;
        #pragma unroll
        for (int ni = 0; ni < 4; ni++) {
            const int col = bn + wn + ni * 8 + tg * 2;
            *(float2*)(g_qkv + (size_t)r0 * (3 * C_) + col) =
                make_float2(acc[mi][ni][0], acc[mi][ni][1]);
            *(float2*)(g_qkv + (size_t)(r0 + 8) * (3 * C_) + col) =
                make_float2(acc[mi][ni][2], acc[mi][ni][3]);
        }
    }
}

// ---------------- 3a) per-chunk outer-product sums, merged 128x128 ----------------
__global__ __launch_bounds__(256) void chunk_g_kernel(const float* __restrict__ decay_ptr) {
    const int j = blockIdx.x;
    const int b = blockIdx.y;
    const float dec = sigmoidf_(decay_ptr[0]);
    const float l2d = log2f(dec);

    __shared__ float Ks[32][128];
    __shared__ float Vs[32][128];

    const int tid = threadIdx.x;
    const int trow = tid >> 4;   // c rows trow*8
    const int tcol = tid & 15;   // d cols tcol*8
    const int r = tid >> 3;      // load row 0..31
    const int q8 = tid & 7;

    float acc[8][8] = {};
    const float* base = g_qkv + ((size_t)b * T_ + (size_t)j * S_) * (3 * C_);

    #pragma unroll
    for (int i0 = 0; i0 < S_; i0 += 32) {
        const float sc = exp2f((float)(S_ - 1 - (i0 + r)) * l2d);
        const float* row = base + (size_t)(i0 + r) * (3 * C_);
        #pragma unroll
        for (int u = 0; u < 4; u++) {
            const int c4 = (q8 + u * 8) * 4;
            float4 kv = *(const float4*)(row + C_ + c4);
            Ks[r][c4 + 0] = kv.x * sc;
            Ks[r][c4 + 1] = kv.y * sc;
            Ks[r][c4 + 2] = kv.z * sc;
            Ks[r][c4 + 3] = kv.w * sc;
            *(float4*)&Vs[r][c4] = *(const float4*)(row + 2 * C_ + c4);
        }
        __syncthreads();
        #pragma unroll
        for (int ii = 0; ii < 32; ii++) {
            float ar[8], br[8];
            *(float4*)&ar[0] = *(const float4*)&Ks[ii][trow * 8];
            *(float4*)&ar[4] = *(const float4*)&Ks[ii][trow * 8 + 4];
            *(float4*)&br[0] = *(const float4*)&Vs[ii][tcol * 8];
            *(float4*)&br[4] = *(const float4*)&Vs[ii][tcol * 8 + 4];
            #pragma unroll
            for (int m = 0; m < 8; m++)
                #pragma unroll
                for (int n = 0; n < 8; n++)
                    acc[m][n] = fmaf(ar[m], br[n], acc[m][n]);
        }
        __syncthreads();
    }

    float* gout = g_G + ((size_t)(b * NCH + j) * C_ * C_);
    #pragma unroll
    for (int m = 0; m < 8; m++) {
        float* grow = gout + (size_t)(trow * 8 + m) * C_ + tcol * 8;
        *(float4*)(grow)     = make_float4(acc[m][0], acc[m][1], acc[m][2], acc[m][3]);
        *(float4*)(grow + 4) = make_float4(acc[m][4], acc[m][5], acc[m][6], acc[m][7]);
    }
}

// ---------------- 3b) scan with batched prefetch ----------------
__global__ void scan_kernel(const float* __restrict__ decay_ptr) {
    const int idx = blockIdx.x * blockDim.x + threadIdx.x;
    const int b = idx >> 12;
    const int e4 = idx & 4095;
    const float dec = sigmoidf_(decay_ptr[0]);
    const float dS = exp2f((float)S_ * log2f(dec));

    const float4* G = (const float4*)(g_G + (size_t)b * NCH * C_ * C_) + e4;
    float4* M = (float4*)(g_M + (size_t)b * NCH * C_ * C_) + e4;

    float4 m = make_float4(0.f, 0.f, 0.f, 0.f);
    #pragma unroll
    for (int jb = 0; jb < NCH; jb += 8) {
        float4 buf[8];
        #pragma unroll
        for (int u = 0; u < 8; u++) buf[u] = G[(size_t)(jb + u) * 4096];
        #pragma unroll
        for (int u = 0; u < 8; u++) {
            M[(size_t)(jb + u) * 4096] = m;
            m.x = fmaf(dS, m.x, buf[u].x);
            m.y = fmaf(dS, m.y, buf[u].y);
            m.z = fmaf(dS, m.z, buf[u].z);
            m.w = fmaf(dS, m.w, buf[u].w);
        }
    }
}

// ---------------- 3c) retrieval per chunk ----------------
__global__ __launch_bounds__(256) void retr_kernel(const float* __restrict__ decay_ptr) {
    const int j = blockIdx.x;
    const int b = blockIdx.y;
    const float dec = sigmoidf_(decay_ptr[0]);
    const float l2d = log2f(dec);

    __shared__ float Qs[32][64];
    __shared__ float Ks2[32][64];
    __shared__ float As[64][64];
    __shared__ float Vs[32][128];

    const int tid = threadIdx.x;
    const float* base = g_qkv + ((size_t)b * T_ + (size_t)j * S_) * (3 * C_);

    {
        const int ti = tid >> 4;
        const int ts = tid & 15;
        const int li = tid >> 2;
        const int lp = tid & 3;

        float acc[4][4] = {};
        for (int c0 = 0; c0 < C_; c0 += 32) {
            #pragma unroll
            for (int u = 0; u < 2; u++) {
                int c = lp * 8 + u * 4;
                float4 qv = *(const float4*)(base + (size_t)li * (3 * C_) + c0 + c);
                Qs[c + 0][li] = qv.x; Qs[c + 1][li] = qv.y;
                Qs[c + 2][li] = qv.z; Qs[c + 3][li] = qv.w;
                float4 kv = *(const float4*)(base + (size_t)li * (3 * C_) + C_ + c0 + c);
                Ks2[c + 0][li] = kv.x; Ks2[c + 1][li] = kv.y;
                Ks2[c + 2][li] = kv.z; Ks2[c + 3][li] = kv.w;
            }
            __syncthreads();
            #pragma unroll
            for (int cc = 0; cc < 32; cc++) {
                float4 a4 = *(const float4*)&Qs[cc][ti * 4];
                float4 b4 = *(const float4*)&Ks2[cc][ts * 4];
                float ar[4] = {a4.x, a4.y, a4.z, a4.w};
                float br[4] = {b4.x, b4.y, b4.z, b4.w};
                #pragma unroll
                for (int m = 0; m < 4; m++)
                    #pragma unroll
                    for (int n = 0; n < 4; n++)
                        acc[m][n] = fmaf(ar[m], br[n], acc[m][n]);
            }
            __syncthreads();
        }
        #pragma unroll
        for (int m = 0; m < 4; m++) {
            const int i = ti * 4 + m;
            #pragma unroll
            for (int n = 0; n < 4; n++) {
                const int s = ts * 4 + n;
                float v = 0.f;
                if (s < i) v = acc[m][n] * exp2f((float)(i - 1 - s) * l2d);
                As[s][i] = v;
            }
        }
    }
    __syncthreads();

    const int ti2 = tid >> 4;
    const int td  = tid & 15;
    const int lr  = tid >> 3;
    const int lq  = tid & 7;

    float accA[4][8] = {};
    float accM[4][8] = {};

    for (int s0 = 0; s0 < S_; s0 += 32) {
        #pragma unroll
        for (int u = 0; u < 4; u++) {
            int c4 = lq + u * 8;
            *(float4*)&Vs[lr][c4 * 4] =
                *(const float4*)(base + (size_t)(s0 + lr) * (3 * C_) + 2 * C_ + c4 * 4);
        }
        __syncthreads();
        #pragma unroll
        for (int ss = 0; ss < 32; ss++) {
            float4 a4 = *(const float4*)&As[s0 + ss][ti2 * 4];
            float4 b0 = *(const float4*)&Vs[ss][td * 8];
            float4 b1 = *(const float4*)&Vs[ss][td * 8 + 4];
            float ar[4] = {a4.x, a4.y, a4.z, a4.w};
            float br[8] = {b0.x, b0.y, b0.z, b0.w, b1.x, b1.y, b1.z, b1.w};
            #pragma unroll
            for (int m = 0; m < 4; m++)
                #pragma unroll
                for (int n = 0; n < 8; n++)
                    accA[m][n] = fmaf(ar[m], br[n], accA[m][n]);
        }
        __syncthreads();
    }

    const float* Mbase = g_M + (size_t)(b * NCH + j) * C_ * C_;
    {
        const int li = tid >> 2;
        const int lp = tid & 3;
        for (int c0 = 0; c0 < C_; c0 += 32) {
            #pragma unroll
            for (int u = 0; u < 2; u++) {
                int c = lp * 8 + u * 4;
                float4 qv = *(const float4*)(base + (size_t)li * (3 * C_) + c0 + c);
                Qs[c + 0][li] = qv.x; Qs[c + 1][li] = qv.y;
                Qs[c + 2][li] = qv.z; Qs[c + 3][li] = qv.w;
            }
            #pragma unroll
            for (int u = 0; u < 4; u++) {
                int c4 = lq + u * 8;
                *(float4*)&Vs[lr][c4 * 4] =
                    *(const float4*)(Mbase + (size_t)(c0 + lr) * C_ + c4 * 4);
            }
            __syncthreads();
            #pragma unroll
            for (int cc = 0; cc < 32; cc++) {
                float4 a4 = *(const float4*)&Qs[cc][ti2 * 4];
                float4 b0 = *(const float4*)&Vs[cc][td * 8];
                float4 b1 = *(const float4*)&Vs[cc][td * 8 + 4];
                float ar[4] = {a4.x, a4.y, a4.z, a4.w};
                float br[8] = {b0.x, b0.y, b0.z, b0.w, b1.x, b1.y, b1.z, b1.w};
                #pragma unroll
                for (int m = 0; m < 4; m++)
                    #pragma unroll
                    for (int n = 0; n < 8; n++)
                        accM[m][n] = fmaf(ar[m], br[n], accM[m][n]);
            }
            __syncthreads();
        }
    }

    float* rout = g_r + ((size_t)b * T_ + (size_t)j * S_) * C_;
    #pragma unroll
    for (int m = 0; m < 4; m++) {
        const int i = ti2 * 4 + m;
        const float di = exp2f((float)i * l2d);
        float o[8];
        #pragma unroll
        for (int n = 0; n < 8; n++) o[n] = fmaf(di, accM[m][n], accA[m][n]);
        *(float4*)(rout + (size_t)i * C_ + td * 8)     = make_float4(o[0], o[1], o[2], o[3]);
        *(float4*)(rout + (size_t)i * C_ + td * 8 + 4) = make_float4(o[4], o[5], o[6], o[7]);
    }
}

// ---------------- 4a) r2 = g_r @ oc, emit bf16 hi/lo [M][64] ----------------
__global__ __launch_bounds__(256) void oc_gemm_kernel(const float* __restrict__ oc) {
    constexpr int BK = 16;
    __shared__ float As[BK][C_];
    __shared__ float Bs[BK][NB2];

    const int tid = threadIdx.x;
    const int bm = blockIdx.x * 128;
    const int trow = tid >> 4;
    const int tcol = tid & 15;

    float acc[8][4] = {};

    for (int k0 = 0; k0 < C_; k0 += BK) {
        #pragma unroll
        for (int t = 0; t < 2; t++) {
            int idx = tid + t * 256;
            int m = idx >> 2, k4 = (idx & 3) * 4;
            float4 a4 = *(const float4*)(g_r + (size_t)(bm + m) * C_ + k0 + k4);
            As[k4 + 0][m] = a4.x; As[k4 + 1][m] = a4.y;
            As[k4 + 2][m] = a4.z; As[k4 + 3][m] = a4.w;
        }
        {
            int k = tid >> 4, n4 = (tid & 15) * 4;
            *(float4*)&Bs[k][n4] = *(const float4*)(oc + (size_t)(k0 + k) * NB2 + n4);
        }
        __syncthreads();
        #pragma unroll
        for (int kk = 0; kk < BK; kk++) {
            float ar[8], br[4];
            *(float4*)&ar[0] = *(const float4*)&As[kk][trow * 8];
            *(float4*)&ar[4] = *(const float4*)&As[kk][trow * 8 + 4];
            *(float4*)&br[0] = *(const float4*)&Bs[kk][tcol * 4];
            #pragma unroll
            for (int i = 0; i < 8; i++)
                #pragma unroll
                for (int jn = 0; jn < 4; jn++)
                    acc[i][jn] = fmaf(ar[i], br[jn], acc[i][jn]);
        }
        __syncthreads();
    }
    #pragma unroll
    for (int i = 0; i < 8; i++) {
        unsigned short h[4], l[4];
        #pragma unroll
        for (int jn = 0; jn < 4; jn++) {
            __nv_bfloat16 hb = __float2bfloat16_rn(acc[i][jn]);
            __nv_bfloat16 lb = __float2bfloat16_rn(acc[i][jn] - __bfloat162float(hb));
            h[jn] = __bfloat16_as_ushort(hb);
            l[jn] = __bfloat16_as_ushort(lb);
        }
        const size_t o = (size_t)(bm + trow * 8 + i) * NB2 + tcol * 4;
        *(uint2*)(g_r2h + o) = make_uint2((uint32_t)h[0] | ((uint32_t)h[1] << 16),
                                          (uint32_t)h[2] | ((uint32_t)h[3] << 16));
        *(uint2*)(g_r2l + o) = make_uint2((uint32_t)l[0] | ((uint32_t)l[1] << 16),
                                          (uint32_t)l[2] | ((uint32_t)l[3] << 16));
    }
}

// ---------------- 4b) out = r2 @ basis^T * scale, bf16x3 + ldmatrix + cp.async ----------------
__global__ __launch_bounds__(256) void out2_mma_kernel(float* __restrict__ Cout,
                                                       const float* __restrict__ scale_ptr) {
    extern __shared__ char sm[];
    const uint32_t sbase = smem_to_u32(sm);
    const int tid = threadIdx.x;
    const int warp = tid >> 5, lane = tid & 31;
    const int bm = blockIdx.y * 128;
    const int bn = blockIdx.x * 128;
    const int wm = (warp >> 2) * 64;
    const int wn = (warp & 3) * 32;

    const int frow = tid >> 2;
    const int fkq = tid & 3;

    const int arow = lane & 15;
    const int akg = lane >> 4;
    const int fA = (arow >> 1) & 3;
    const int brow = ((lane >> 4) & 1) * 8 + (lane & 7);
    const int bkg = (lane >> 3) & 1;
    const int fB = (brow >> 1) & 3;

    float acc[4][4][4] = {};

    auto fill = [&](int stage, int c0) {
        const uint32_t nb = sbase + stage * QBUF;
        #pragma unroll
        for (int it = 0; it < 2; it++) {
            const int row = frow + it * 64;
            const uint32_t dst = nb + row * 64 + ((fkq ^ ((row >> 1) & 3)) * 16);
            CP_ASYNC16(dst,         g_r2h + (size_t)(bm + row) * NB2 + c0 + fkq * 8);
            CP_ASYNC16(dst + 8192,  g_r2l + (size_t)(bm + row) * NB2 + c0 + fkq * 8);
            CP_ASYNC16(dst + 16384, g_bh + (size_t)(bn + row) * NB2 + c0 + fkq * 8);
            CP_ASYNC16(dst + 24576, g_bl + (size_t)(bn + row) * NB2 + c0 + fkq * 8);
        }
    };

    fill(0, 0);
    CP_COMMIT();

    for (int ch = 0; ch < 2; ch++) {
        if (ch + 1 < 2) { fill(ch + 1, 32); CP_COMMIT(); }
        if (ch == 0) { CP_WAIT1(); } else { CP_WAIT0(); }
        __syncthreads();

        const uint32_t cb = sbase + ch * QBUF;
        #pragma unroll
        for (int ks = 0; ks < 2; ks++) {
            uint32_t a_h[4][4], a_l[4][4];
            const uint32_t achunk = (uint32_t)(((ks * 2 + akg) ^ fA) * 16);
            #pragma unroll
            for (int mi = 0; mi < 4; mi++) {
                const uint32_t aaddr = cb + (uint32_t)((wm + mi * 16 + arow) * 64) + achunk;
                ldsm_x4(a_h[mi], aaddr);
                ldsm_x4(a_l[mi], aaddr + 8192);
            }
            uint32_t b_h[4][2], b_l[4][2];
            const uint32_t bchunk = (uint32_t)(((ks * 2 + bkg) ^ fB) * 16);
            #pragma unroll
            for (int nip = 0; nip < 2; nip++) {
                const uint32_t baddr = cb + 16384 +
                    (uint32_t)((wn + nip * 16 + brow) * 64) + bchunk;
                uint32_t rh[4], rl[4];
                ldsm_x4(rh, baddr);
                ldsm_x4(rl, baddr + 8192);
                b_h[nip * 2 + 0][0] = rh[0]; b_h[nip * 2 + 0][1] = rh[1];
                b_h[nip * 2 + 1][0] = rh[2]; b_h[nip * 2 + 1][1] = rh[3];
                b_l[nip * 2 + 0][0] = rl[0]; b_l[nip * 2 + 0][1] = rl[1];
                b_l[nip * 2 + 1][0] = rl[2]; b_l[nip * 2 + 1][1] = rl[3];
            }
            #pragma unroll
            for (int mi = 0; mi < 4; mi++)
                #pragma unroll
                for (int ni = 0; ni < 4; ni++) {
                    mma_bf16(acc[mi][ni], a_l[mi], b_h[ni]);
                    mma_bf16(acc[mi][ni], a_h[mi], b_l[ni]);
                    mma_bf16(acc[mi][ni], a_h[mi], b_h[ni]);
                }
        }
        __syncthreads();
    }

    const float sc = *scale_ptr;
    const int g = lane >> 2, tg = lane & 3;
    #pragma unroll
    for (int mi = 0; mi < 4; mi++) {
        const int r0 = bm + wm + mi * 16 + g;
        #pragma unroll
        for (int ni = 0; ni < 4; ni++) {
            const int col = bn + wn + ni * 8 + tg * 2;
            *(float2*)(Cout + (size_t)r0 * V_ + col) =
                make_float2(acc[mi][ni][0] * sc, acc[mi][ni][1] * sc);
            *(float2*)(Cout + (size_t)(r0 + 8) * V_ + col) =
                make_float2(acc[mi][ni][2] * sc, acc[mi][ni][3] * sc);
        }
    }
}

// ---------------- launch ----------------
extern "C" void kernel_launch(void* const* d_in, const int* in_sizes, int n_in,
                              void* d_out, int out_size) {
    const float* x      = (const float*)d_in[0];
    const float* basis  = (const float*)d_in[1];
    const float* qc     = (const float*)d_in[2];
    const float* kc     = (const float*)d_in[3];
    const float* vc     = (const float*)d_in[4];
    const float* oc     = (const float*)d_in[5];
    const float* decay  = (const float*)d_in[6];
    const float* oscale = (const float*)d_in[7];
    float* out = (float*)d_out;

    cudaFuncSetAttribute(qkv_mma_kernel, cudaFuncAttributeMaxDynamicSharedMemorySize, 3 * QBUF);
    cudaFuncSetAttribute(out2_mma_kernel, cudaFuncAttributeMaxDynamicSharedMemorySize, 2 * QBUF);

    cvt_x_kernel<<<(MT * V_) / 1024, 256>>>(x);
    cvt_basis_kernel<<<(V_ * NB2) / 1024, 256>>>(basis);
    logits_kernel<<<dim3(3, 8), 256>>>(basis, qc, kc, vc);
    softmax_w_kernel<<<3 * C_, 1024>>>();
    qkv_mma_kernel<<<dim3(3, MT / 128), 256, 3 * QBUF>>>();
    chunk_g_kernel<<<dim3(NCH, B_), 256>>>(decay);
    scan_kernel<<<128, 256>>>(decay);
    retr_kernel<<<dim3(NCH, B_), 256>>>(decay);
    oc_gemm_kernel<<<MT / 128, 256>>>(oc);
    out2_mma_kernel<<<dim3(V_ / 128, MT / 128), 256, 2 * QBUF>>>(out, oscale);
}

// round 10
// speedup vs baseline: 1.9096x; 1.0258x over previous
#include <cuda_runtime.h>
#include <cuda_bf16.h>
#include <math.h>
#include <stdint.h>

#define B_ 8
#define T_ 2048
#define V_ 1024
#define C_ 128
#define NB2 64   // 2*NB
#define S_ 64    // chunk size
#define NCH 32   // T_/S_
#define MT (B_ * T_)   // 16384

// ---------------- device scratch ----------------
__device__ unsigned short g_xh16[(size_t)MT * V_];   // x hi bf16, row-major [M][K]
__device__ unsigned short g_xl16[(size_t)MT * V_];   // x lo bf16
__device__ unsigned short g_wth[3 * C_ * V_];        // W^T hi bf16, [N][K]
__device__ unsigned short g_wtl[3 * C_ * V_];        // W^T lo bf16
__device__ float g_logits[3 * C_ * V_];              // logits [N][V]
__device__ unsigned short g_bh[V_ * NB2];            // basis hi bf16 [N][K]
__device__ unsigned short g_bl[V_ * NB2];            // basis lo bf16
__device__ unsigned short g_r2h[(size_t)MT * NB2];   // r2 hi bf16 [M][64]
__device__ unsigned short g_r2l[(size_t)MT * NB2];   // r2 lo bf16
__device__ float g_qkv[(size_t)MT * 3 * C_];         // (B*T, 384)
__device__ float g_G[B_ * NCH * C_ * C_];            // per-chunk outer-product sums
__device__ float g_M[B_ * NCH * C_ * C_];            // chunk-boundary states

__device__ __forceinline__ float sigmoidf_(float x) { return 1.0f / (1.0f + expf(-x)); }

__device__ __forceinline__ void mma_bf16(float* c, const uint32_t* a, const uint32_t* b) {
    asm volatile(
        "mma.sync.aligned.m16n8k16.row.col.f32.bf16.bf16.f32 "
        "{%0,%1,%2,%3}, {%4,%5,%6,%7}, {%8,%9}, {%0,%1,%2,%3};"
        : "+f"(c[0]), "+f"(c[1]), "+f"(c[2]), "+f"(c[3])
        : "r"(a[0]), "r"(a[1]), "r"(a[2]), "r"(a[3]), "r"(b[0]), "r"(b[1]));
}

__device__ __forceinline__ uint32_t smem_to_u32(const void* p) {
    uint32_t a;
    asm("{ .reg .u64 t; cvta.to.shared.u64 t, %1; cvt.u32.u64 %0, t; }" : "=r"(a) : "l"(p));
    return a;
}

__device__ __forceinline__ void ldsm_x4(uint32_t* r, uint32_t addr) {
    asm volatile("ldmatrix.sync.aligned.m8n8.x4.shared.b16 {%0,%1,%2,%3}, [%4];"
                 : "=r"(r[0]), "=r"(r[1]), "=r"(r[2]), "=r"(r[3]) : "r"(addr));
}

#define CP_ASYNC16(dst, src) \
    asm volatile("cp.async.cg.shared.global [%0], [%1], 16;" :: "r"(dst), "l"(src))
#define CP_COMMIT() asm volatile("cp.async.commit_group;" ::: "memory")
#define CP_WAIT0()  asm volatile("cp.async.wait_group 0;" ::: "memory")
#define CP_WAIT1()  asm volatile("cp.async.wait_group 1;" ::: "memory")

// ---------------- 0a) convert x to bf16 hi/lo, row-major [M][K] ----------------
__global__ __launch_bounds__(256) void cvt_x_kernel(const float* __restrict__ x) {
    const size_t i = ((size_t)blockIdx.x * 256 + threadIdx.x) * 4;
    float4 v = *(const float4*)(x + i);
    float vv[4] = {v.x, v.y, v.z, v.w};
    unsigned short h[4], l[4];
    #pragma unroll
    for (int u = 0; u < 4; u++) {
        __nv_bfloat16 hb = __float2bfloat16_rn(vv[u]);
        __nv_bfloat16 lb = __float2bfloat16_rn(vv[u] - __bfloat162float(hb));
        h[u] = __bfloat16_as_ushort(hb);
        l[u] = __bfloat16_as_ushort(lb);
    }
    *(uint2*)(g_xh16 + i) = make_uint2((uint32_t)h[0] | ((uint32_t)h[1] << 16),
                                       (uint32_t)h[2] | ((uint32_t)h[3] << 16));
    *(uint2*)(g_xl16 + i) = make_uint2((uint32_t)l[0] | ((uint32_t)l[1] << 16),
                                       (uint32_t)l[2] | ((uint32_t)l[3] << 16));
}

// ---------------- 0b) convert basis to bf16 hi/lo [N][K] ----------------
__global__ __launch_bounds__(256) void cvt_basis_kernel(const float* __restrict__ basis) {
    const size_t i = ((size_t)blockIdx.x * 256 + threadIdx.x) * 4;
    float4 v = *(const float4*)(basis + i);
    float vv[4] = {v.x, v.y, v.z, v.w};
    unsigned short h[4], l[4];
    #pragma unroll
    for (int u = 0; u < 4; u++) {
        __nv_bfloat16 hb = __float2bfloat16_rn(vv[u]);
        __nv_bfloat16 lb = __float2bfloat16_rn(vv[u] - __bfloat162float(hb));
        h[u] = __bfloat16_as_ushort(hb);
        l[u] = __bfloat16_as_ushort(lb);
    }
    *(uint2*)(g_bh + i) = make_uint2((uint32_t)h[0] | ((uint32_t)h[1] << 16),
                                     (uint32_t)h[2] | ((uint32_t)h[3] << 16));
    *(uint2*)(g_bl + i) = make_uint2((uint32_t)l[0] | ((uint32_t)l[1] << 16),
                                     (uint32_t)l[2] | ((uint32_t)l[3] << 16));
}

// ---------------- 1a) logits = coeffs @ basis^T, written [N][V] ----------------
__global__ __launch_bounds__(256) void logits_kernel(const float* __restrict__ basis,
                                                     const float* __restrict__ qc,
                                                     const float* __restrict__ kc,
                                                     const float* __restrict__ vc) {
    const int w = blockIdx.x;
    const int vb = blockIdx.y;
    const float* coef = (w == 0 ? qc : (w == 1 ? kc : vc));

    __shared__ float Cs[NB2][C_ + 4];
    __shared__ float Bs[NB2][C_ + 4];

    const int tid = threadIdx.x;
    const int lr = tid >> 1;
    const int lk = (tid & 1) * 32;

    #pragma unroll
    for (int u = 0; u < 8; u++) {
        const int k = lk + u * 4;
        float4 cv = *(const float4*)(coef + (size_t)lr * NB2 + k);
        Cs[k + 0][lr] = cv.x; Cs[k + 1][lr] = cv.y;
        Cs[k + 2][lr] = cv.z; Cs[k + 3][lr] = cv.w;
        float4 bv = *(const float4*)(basis + (size_t)(vb * 128 + lr) * NB2 + k);
        Bs[k + 0][lr] = bv.x; Bs[k + 1][lr] = bv.y;
        Bs[k + 2][lr] = bv.z; Bs[k + 3][lr] = bv.w;
    }
    __syncthreads();

    const int trow = tid >> 4;
    const int tcol = tid & 15;
    float acc[8][8] = {};
    #pragma unroll
    for (int kk = 0; kk < NB2; kk++) {
        float ar[8], br[8];
        *(float4*)&ar[0] = *(const float4*)&Cs[kk][trow * 8];
        *(float4*)&ar[4] = *(const float4*)&Cs[kk][trow * 8 + 4];
        *(float4*)&br[0] = *(const float4*)&Bs[kk][tcol * 8];
        *(float4*)&br[4] = *(const float4*)&Bs[kk][tcol * 8 + 4];
        #pragma unroll
        for (int i = 0; i < 8; i++)
            #pragma unroll
            for (int jn = 0; jn < 8; jn++)
                acc[i][jn] = fmaf(ar[i], br[jn], acc[i][jn]);
    }
    #pragma unroll
    for (int i = 0; i < 8; i++) {
        float* lrow = g_logits + (size_t)(w * C_ + trow * 8 + i) * V_ + vb * 128 + tcol * 8;
        *(float4*)(lrow)     = make_float4(acc[i][0], acc[i][1], acc[i][2], acc[i][3]);
        *(float4*)(lrow + 4) = make_float4(acc[i][4], acc[i][5], acc[i][6], acc[i][7]);
    }
}

// ---------------- 1b) column softmax over V, 256 threads x 4, emit bf16 hi/lo ----------------
__global__ __launch_bounds__(256) void softmax_w_kernel() {
    const int n = blockIdx.x;
    const int tid = threadIdx.x;
    __shared__ float red[8];
    __shared__ float sval;

    float4 s4 = *(const float4*)(g_logits + (size_t)n * V_ + tid * 4);
    float s[4] = {s4.x, s4.y, s4.z, s4.w};

    float m = fmaxf(fmaxf(s[0], s[1]), fmaxf(s[2], s[3]));
    #pragma unroll
    for (int o = 16; o; o >>= 1) m = fmaxf(m, __shfl_xor_sync(0xffffffffu, m, o));
    if ((tid & 31) == 0) red[tid >> 5] = m;
    __syncthreads();
    if (tid < 8) {
        float t = red[tid];
        #pragma unroll
        for (int o = 4; o; o >>= 1) t = fmaxf(t, __shfl_xor_sync(0xffu, t, o));
        if (tid == 0) sval = t;
    }
    __syncthreads();
    const float M = sval;

    float e[4];
    float su = 0.f;
    #pragma unroll
    for (int u = 0; u < 4; u++) { e[u] = expf(s[u] - M); su += e[u]; }
    #pragma unroll
    for (int o = 16; o; o >>= 1) su += __shfl_xor_sync(0xffffffffu, su, o);
    if ((tid & 31) == 0) red[tid >> 5] = su;
    __syncthreads();
    if (tid < 8) {
        float t = red[tid];
        #pragma unroll
        for (int o = 4; o; o >>= 1) t += __shfl_xor_sync(0xffu, t, o);
        if (tid == 0) sval = t;
    }
    __syncthreads();
    const float inv = 1.0f / sval;

    unsigned short h[4], l[4];
    #pragma unroll
    for (int u = 0; u < 4; u++) {
        const float val = e[u] * inv;
        __nv_bfloat16 hb = __float2bfloat16_rn(val);
        __nv_bfloat16 lb = __float2bfloat16_rn(val - __bfloat162float(hb));
        h[u] = __bfloat16_as_ushort(hb);
        l[u] = __bfloat16_as_ushort(lb);
    }
    const size_t o = (size_t)n * V_ + tid * 4;
    *(uint2*)(g_wth + o) = make_uint2((uint32_t)h[0] | ((uint32_t)h[1] << 16),
                                      (uint32_t)h[2] | ((uint32_t)h[3] << 16));
    *(uint2*)(g_wtl + o) = make_uint2((uint32_t)l[0] | ((uint32_t)l[1] << 16),
                                      (uint32_t)l[2] | ((uint32_t)l[3] << 16));
}

// ---------------- 2) QKV GEMM: bf16x3 mma.sync + ldmatrix + 3-stage cp.async ----------------
#define QBUF 32768
__global__ __launch_bounds__(256) void qkv_mma_kernel() {
    extern __shared__ char sm[];
    const uint32_t sbase = smem_to_u32(sm);
    const int tid = threadIdx.x;
    const int warp = tid >> 5, lane = tid & 31;
    const int bm = blockIdx.y * 128;
    const int bn = blockIdx.x * 128;
    const int wm = (warp >> 2) * 64;
    const int wn = (warp & 3) * 32;

    const int frow = tid >> 2;
    const int fkq = tid & 3;

    const int arow = lane & 15;
    const int akg = lane >> 4;
    const int fA = (arow >> 1) & 3;
    const int brow = ((lane >> 4) & 1) * 8 + (lane & 7);
    const int bkg = (lane >> 3) & 1;
    const int fB = (brow >> 1) & 3;

    float acc[4][4][4] = {};

    auto fill = [&](int stage, int c0) {
        const uint32_t nb = sbase + stage * QBUF;
        #pragma unroll
        for (int it = 0; it < 2; it++) {
            const int row = frow + it * 64;
            const uint32_t dst = nb + row * 64 + ((fkq ^ ((row >> 1) & 3)) * 16);
            CP_ASYNC16(dst,         g_xh16 + (size_t)(bm + row) * V_ + c0 + fkq * 8);
            CP_ASYNC16(dst + 8192,  g_xl16 + (size_t)(bm + row) * V_ + c0 + fkq * 8);
            CP_ASYNC16(dst + 16384, g_wth + (size_t)(bn + row) * V_ + c0 + fkq * 8);
            CP_ASYNC16(dst + 24576, g_wtl + (size_t)(bn + row) * V_ + c0 + fkq * 8);
        }
    };

    fill(0, 0);  CP_COMMIT();
    fill(1, 32); CP_COMMIT();

    for (int ch = 0; ch < 32; ch++) {
        CP_WAIT1();
        __syncthreads();

        const uint32_t cb = sbase + (ch % 3) * QBUF;
        #pragma unroll
        for (int ks = 0; ks < 2; ks++) {
            uint32_t a_h[4][4], a_l[4][4];
            const uint32_t achunk = (uint32_t)(((ks * 2 + akg) ^ fA) * 16);
            #pragma unroll
            for (int mi = 0; mi < 4; mi++) {
                const uint32_t aaddr = cb + (uint32_t)((wm + mi * 16 + arow) * 64) + achunk;
                ldsm_x4(a_h[mi], aaddr);
                ldsm_x4(a_l[mi], aaddr + 8192);
            }
            uint32_t b_h[4][2], b_l[4][2];
            const uint32_t bchunk = (uint32_t)(((ks * 2 + bkg) ^ fB) * 16);
            #pragma unroll
            for (int nip = 0; nip < 2; nip++) {
                const uint32_t baddr = cb + 16384 +
                    (uint32_t)((wn + nip * 16 + brow) * 64) + bchunk;
                uint32_t rh[4], rl[4];
                ldsm_x4(rh, baddr);
                ldsm_x4(rl, baddr + 8192);
                b_h[nip * 2 + 0][0] = rh[0]; b_h[nip * 2 + 0][1] = rh[1];
                b_h[nip * 2 + 1][0] = rh[2]; b_h[nip * 2 + 1][1] = rh[3];
                b_l[nip * 2 + 0][0] = rl[0]; b_l[nip * 2 + 0][1] = rl[1];
                b_l[nip * 2 + 1][0] = rl[2]; b_l[nip * 2 + 1][1] = rl[3];
            }
            #pragma unroll
            for (int mi = 0; mi < 4; mi++)
                #pragma unroll
                for (int ni = 0; ni < 4; ni++) {
                    mma_bf16(acc[mi][ni], a_l[mi], b_h[ni]);
                    mma_bf16(acc[mi][ni], a_h[mi], b_l[ni]);
                    mma_bf16(acc[mi][ni], a_h[mi], b_h[ni]);
                }
        }

        __syncthreads();
        if (ch + 2 < 32) fill((ch + 2) % 3, (ch + 2) * 32);
        CP_COMMIT();
    }

    const int g = lane >> 2, tg = lane & 3;
    #pragma unroll
    for (int mi = 0; mi < 4; mi++) {
        const int r0 = bm + wm + mi * 16 + g;
        #pragma unroll
        for (int ni = 0; ni < 4; ni++) {
            const int col = bn + wn + ni * 8 + tg * 2;
            *(float2*)(g_qkv + (size_t)r0 * (3 * C_) + col) =
                make_float2(acc[mi][ni][0], acc[mi][ni][1]);
            *(float2*)(g_qkv + (size_t)(r0 + 8) * (3 * C_) + col) =
                make_float2(acc[mi][ni][2], acc[mi][ni][3]);
        }
    }
}

// ---------------- 3a) per-chunk outer-product sums, merged 128x128 ----------------
__global__ __launch_bounds__(256) void chunk_g_kernel(const float* __restrict__ decay_ptr) {
    const int j = blockIdx.x;
    const int b = blockIdx.y;
    const float dec = sigmoidf_(decay_ptr[0]);
    const float l2d = log2f(dec);

    __shared__ float Ks[32][128];
    __shared__ float Vs[32][128];

    const int tid = threadIdx.x;
    const int trow = tid >> 4;
    const int tcol = tid & 15;
    const int r = tid >> 3;
    const int q8 = tid & 7;

    float acc[8][8] = {};
    const float* base = g_qkv + ((size_t)b * T_ + (size_t)j * S_) * (3 * C_);

    #pragma unroll
    for (int i0 = 0; i0 < S_; i0 += 32) {
        const float sc = exp2f((float)(S_ - 1 - (i0 + r)) * l2d);
        const float* row = base + (size_t)(i0 + r) * (3 * C_);
        #pragma unroll
        for (int u = 0; u < 4; u++) {
            const int c4 = (q8 + u * 8) * 4;
            float4 kv = *(const float4*)(row + C_ + c4);
            Ks[r][c4 + 0] = kv.x * sc;
            Ks[r][c4 + 1] = kv.y * sc;
            Ks[r][c4 + 2] = kv.z * sc;
            Ks[r][c4 + 3] = kv.w * sc;
            *(float4*)&Vs[r][c4] = *(const float4*)(row + 2 * C_ + c4);
        }
        __syncthreads();
        #pragma unroll
        for (int ii = 0; ii < 32; ii++) {
            float ar[8], br[8];
            *(float4*)&ar[0] = *(const float4*)&Ks[ii][trow * 8];
            *(float4*)&ar[4] = *(const float4*)&Ks[ii][trow * 8 + 4];
            *(float4*)&br[0] = *(const float4*)&Vs[ii][tcol * 8];
            *(float4*)&br[4] = *(const float4*)&Vs[ii][tcol * 8 + 4];
            #pragma unroll
            for (int m = 0; m < 8; m++)
                #pragma unroll
                for (int n = 0; n < 8; n++)
                    acc[m][n] = fmaf(ar[m], br[n], acc[m][n]);
        }
        __syncthreads();
    }

    float* gout = g_G + ((size_t)(b * NCH + j) * C_ * C_);
    #pragma unroll
    for (int m = 0; m < 8; m++) {
        float* grow = gout + (size_t)(trow * 8 + m) * C_ + tcol * 8;
        *(float4*)(grow)     = make_float4(acc[m][0], acc[m][1], acc[m][2], acc[m][3]);
        *(float4*)(grow + 4) = make_float4(acc[m][4], acc[m][5], acc[m][6], acc[m][7]);
    }
}

// ---------------- 3b) scan with batched prefetch ----------------
__global__ void scan_kernel(const float* __restrict__ decay_ptr) {
    const int idx = blockIdx.x * blockDim.x + threadIdx.x;
    const int b = idx >> 12;
    const int e4 = idx & 4095;
    const float dec = sigmoidf_(decay_ptr[0]);
    const float dS = exp2f((float)S_ * log2f(dec));

    const float4* G = (const float4*)(g_G + (size_t)b * NCH * C_ * C_) + e4;
    float4* M = (float4*)(g_M + (size_t)b * NCH * C_ * C_) + e4;

    float4 m = make_float4(0.f, 0.f, 0.f, 0.f);
    #pragma unroll
    for (int jb = 0; jb < NCH; jb += 8) {
        float4 buf[8];
        #pragma unroll
        for (int u = 0; u < 8; u++) buf[u] = G[(size_t)(jb + u) * 4096];
        #pragma unroll
        for (int u = 0; u < 8; u++) {
            M[(size_t)(jb + u) * 4096] = m;
            m.x = fmaf(dS, m.x, buf[u].x);
            m.y = fmaf(dS, m.y, buf[u].y);
            m.z = fmaf(dS, m.z, buf[u].z);
            m.w = fmaf(dS, m.w, buf[u].w);
        }
    }
}

// ---------------- 3c) retrieval per chunk + fused r2 = R @ oc ----------------
__global__ __launch_bounds__(256) void retr_kernel(const float* __restrict__ decay_ptr,
                                                   const float* __restrict__ oc) {
    const int j = blockIdx.x;
    const int b = blockIdx.y;
    const float dec = sigmoidf_(decay_ptr[0]);
    const float l2d = log2f(dec);

    __shared__ char buf[49152];
    float (*Qs)[64]  = (float(*)[64])(buf);            // 8 KB
    float (*Ks2)[64] = (float(*)[64])(buf + 8192);     // 8 KB
    float (*As)[64]  = (float(*)[64])(buf + 16384);    // 16 KB
    float (*Vs)[128] = (float(*)[128])(buf + 32768);   // 16 KB
    float* Rs = (float*)buf;                           // epilogue reuse: [64][132] = 33.8 KB

    const int tid = threadIdx.x;
    const float* base = g_qkv + ((size_t)b * T_ + (size_t)j * S_) * (3 * C_);

    {
        const int ti = tid >> 4;
        const int ts = tid & 15;
        const int li = tid >> 2;
        const int lp = tid & 3;

        float acc[4][4] = {};
        for (int c0 = 0; c0 < C_; c0 += 32) {
            #pragma unroll
            for (int u = 0; u < 2; u++) {
                int c = lp * 8 + u * 4;
                float4 qv = *(const float4*)(base + (size_t)li * (3 * C_) + c0 + c);
                Qs[c + 0][li] = qv.x; Qs[c + 1][li] = qv.y;
                Qs[c + 2][li] = qv.z; Qs[c + 3][li] = qv.w;
                float4 kv = *(const float4*)(base + (size_t)li * (3 * C_) + C_ + c0 + c);
                Ks2[c + 0][li] = kv.x; Ks2[c + 1][li] = kv.y;
                Ks2[c + 2][li] = kv.z; Ks2[c + 3][li] = kv.w;
            }
            __syncthreads();
            #pragma unroll
            for (int cc = 0; cc < 32; cc++) {
                float4 a4 = *(const float4*)&Qs[cc][ti * 4];
                float4 b4 = *(const float4*)&Ks2[cc][ts * 4];
                float ar[4] = {a4.x, a4.y, a4.z, a4.w};
                float br[4] = {b4.x, b4.y, b4.z, b4.w};
                #pragma unroll
                for (int m = 0; m < 4; m++)
                    #pragma unroll
                    for (int n = 0; n < 4; n++)
                        acc[m][n] = fmaf(ar[m], br[n], acc[m][n]);
            }
            __syncthreads();
        }
        #pragma unroll
        for (int m = 0; m < 4; m++) {
            const int i = ti * 4 + m;
            #pragma unroll
            for (int n = 0; n < 4; n++) {
                const int s = ts * 4 + n;
                float v = 0.f;
                if (s < i) v = acc[m][n] * exp2f((float)(i - 1 - s) * l2d);
                As[s][i] = v;
            }
        }
    }
    __syncthreads();

    const int ti2 = tid >> 4;
    const int td  = tid & 15;
    const int lr  = tid >> 3;
    const int lq  = tid & 7;

    float accA[4][8] = {};
    float accM[4][8] = {};

    for (int s0 = 0; s0 < S_; s0 += 32) {
        #pragma unroll
        for (int u = 0; u < 4; u++) {
            int c4 = lq + u * 8;
            *(float4*)&Vs[lr][c4 * 4] =
                *(const float4*)(base + (size_t)(s0 + lr) * (3 * C_) + 2 * C_ + c4 * 4);
        }
        __syncthreads();
        #pragma unroll
        for (int ss = 0; ss < 32; ss++) {
            float4 a4 = *(const float4*)&As[s0 + ss][ti2 * 4];
            float4 b0 = *(const float4*)&Vs[ss][td * 8];
            float4 b1 = *(const float4*)&Vs[ss][td * 8 + 4];
            float ar[4] = {a4.x, a4.y, a4.z, a4.w};
            float br[8] = {b0.x, b0.y, b0.z, b0.w, b1.x, b1.y, b1.z, b1.w};
            #pragma unroll
            for (int m = 0; m < 4; m++)
                #pragma unroll
                for (int n = 0; n < 8; n++)
                    accA[m][n] = fmaf(ar[m], br[n], accA[m][n]);
        }
        __syncthreads();
    }

    const float* Mbase = g_M + (size_t)(b * NCH + j) * C_ * C_;
    {
        const int li = tid >> 2;
        const int lp = tid & 3;
        for (int c0 = 0; c0 < C_; c0 += 32) {
            #pragma unroll
            for (int u = 0; u < 2; u++) {
                int c = lp * 8 + u * 4;
                float4 qv = *(const float4*)(base + (size_t)li * (3 * C_) + c0 + c);
                Qs[c + 0][li] = qv.x; Qs[c + 1][li] = qv.y;
                Qs[c + 2][li] = qv.z; Qs[c + 3][li] = qv.w;
            }
            #pragma unroll
            for (int u = 0; u < 4; u++) {
                int c4 = lq + u * 8;
                *(float4*)&Vs[lr][c4 * 4] =
                    *(const float4*)(Mbase + (size_t)(c0 + lr) * C_ + c4 * 4);
            }
            __syncthreads();
            #pragma unroll
            for (int cc = 0; cc < 32; cc++) {
                float4 a4 = *(const float4*)&Qs[cc][ti2 * 4];
                float4 b0 = *(const float4*)&Vs[cc][td * 8];
                float4 b1 = *(const float4*)&Vs[cc][td * 8 + 4];
                float ar[4] = {a4.x, a4.y, a4.z, a4.w};
                float br[8] = {b0.x, b0.y, b0.z, b0.w, b1.x, b1.y, b1.z, b1.w};
                #pragma unroll
                for (int m = 0; m < 4; m++)
                    #pragma unroll
                    for (int n = 0; n < 8; n++)
                        accM[m][n] = fmaf(ar[m], br[n], accM[m][n]);
            }
            __syncthreads();
        }
    }

    // ---- combine into Rs[i][132] (reuses buf; all prior smem is dead) ----
    __syncthreads();
    #pragma unroll
    for (int m = 0; m < 4; m++) {
        const int i = ti2 * 4 + m;
        const float di = exp2f((float)i * l2d);
        #pragma unroll
        for (int n = 0; n < 8; n++)
            Rs[i * 132 + td * 8 + n] = fmaf(di, accM[m][n], accA[m][n]);
    }
    __syncthreads();

    // ---- fused r2 = R (64x128) @ oc (128x64), emit bf16 hi/lo ----
    {
        const int i0 = (tid >> 4) * 4;   // rows
        const int j0 = (tid & 15) * 4;   // cols
        float racc[4][4] = {};
        #pragma unroll 4
        for (int d4 = 0; d4 < 128; d4 += 4) {
            float4 a0 = *(const float4*)&Rs[(i0 + 0) * 132 + d4];
            float4 a1 = *(const float4*)&Rs[(i0 + 1) * 132 + d4];
            float4 a2 = *(const float4*)&Rs[(i0 + 2) * 132 + d4];
            float4 a3 = *(const float4*)&Rs[(i0 + 3) * 132 + d4];
            float am[4][4] = {{a0.x, a0.y, a0.z, a0.w},
                              {a1.x, a1.y, a1.z, a1.w},
                              {a2.x, a2.y, a2.z, a2.w},
                              {a3.x, a3.y, a3.z, a3.w}};
            #pragma unroll
            for (int dd = 0; dd < 4; dd++) {
                float4 bv = __ldg((const float4*)(oc + (size_t)(d4 + dd) * NB2 + j0));
                float br[4] = {bv.x, bv.y, bv.z, bv.w};
                #pragma unroll
                for (int ii = 0; ii < 4; ii++)
                    #pragma unroll
                    for (int jj = 0; jj < 4; jj++)
                        racc[ii][jj] = fmaf(am[ii][dd], br[jj], racc[ii][jj]);
            }
        }
        const size_t mbase = (size_t)b * T_ + (size_t)j * S_;
        #pragma unroll
        for (int ii = 0; ii < 4; ii++) {
            unsigned short h[4], l[4];
            #pragma unroll
            for (int jj = 0; jj < 4; jj++) {
                __nv_bfloat16 hb = __float2bfloat16_rn(racc[ii][jj]);
                __nv_bfloat16 lb = __float2bfloat16_rn(racc[ii][jj] - __bfloat162float(hb));
                h[jj] = __bfloat16_as_ushort(hb);
                l[jj] = __bfloat16_as_ushort(lb);
            }
            const size_t o = (mbase + i0 + ii) * NB2 + j0;
            *(uint2*)(g_r2h + o) = make_uint2((uint32_t)h[0] | ((uint32_t)h[1] << 16),
                                              (uint32_t)h[2] | ((uint32_t)h[3] << 16));
            *(uint2*)(g_r2l + o) = make_uint2((uint32_t)l[0] | ((uint32_t)l[1] << 16),
                                              (uint32_t)l[2] | ((uint32_t)l[3] << 16));
        }
    }
}

// ---------------- 4) out = r2 @ basis^T * scale, bf16x3 + ldmatrix + cp.async ----------------
__global__ __launch_bounds__(256) void out2_mma_kernel(float* __restrict__ Cout,
                                                       const float* __restrict__ scale_ptr) {
    extern __shared__ char sm[];
    const uint32_t sbase = smem_to_u32(sm);
    const int tid = threadIdx.x;
    const int warp = tid >> 5, lane = tid & 31;
    const int bm = blockIdx.y * 128;
    const int bn = blockIdx.x * 128;
    const int wm = (warp >> 2) * 64;
    const int wn = (warp & 3) * 32;

    const int frow = tid >> 2;
    const int fkq = tid & 3;

    const int arow = lane & 15;
    const int akg = lane >> 4;
    const int fA = (arow >> 1) & 3;
    const int brow = ((lane >> 4) & 1) * 8 + (lane & 7);
    const int bkg = (lane >> 3) & 1;
    const int fB = (brow >> 1) & 3;

    float acc[4][4][4] = {};

    auto fill = [&](int stage, int c0) {
        const uint32_t nb = sbase + stage * QBUF;
        #pragma unroll
        for (int it = 0; it < 2; it++) {
            const int row = frow + it * 64;
            const uint32_t dst = nb + row * 64 + ((fkq ^ ((row >> 1) & 3)) * 16);
            CP_ASYNC16(dst,         g_r2h + (size_t)(bm + row) * NB2 + c0 + fkq * 8);
            CP_ASYNC16(dst + 8192,  g_r2l + (size_t)(bm + row) * NB2 + c0 + fkq * 8);
            CP_ASYNC16(dst + 16384, g_bh + (size_t)(bn + row) * NB2 + c0 + fkq * 8);
            CP_ASYNC16(dst + 24576, g_bl + (size_t)(bn + row) * NB2 + c0 + fkq * 8);
        }
    };

    fill(0, 0);
    CP_COMMIT();

    for (int ch = 0; ch < 2; ch++) {
        if (ch + 1 < 2) { fill(ch + 1, 32); CP_COMMIT(); }
        if (ch == 0) { CP_WAIT1(); } else { CP_WAIT0(); }
        __syncthreads();

        const uint32_t cb = sbase + ch * QBUF;
        #pragma unroll
        for (int ks = 0; ks < 2; ks++) {
            uint32_t a_h[4][4], a_l[4][4];
            const uint32_t achunk = (uint32_t)(((ks * 2 + akg) ^ fA) * 16);
            #pragma unroll
            for (int mi = 0; mi < 4; mi++) {
                const uint32_t aaddr = cb + (uint32_t)((wm + mi * 16 + arow) * 64) + achunk;
                ldsm_x4(a_h[mi], aaddr);
                ldsm_x4(a_l[mi], aaddr + 8192);
            }
            uint32_t b_h[4][2], b_l[4][2];
            const uint32_t bchunk = (uint32_t)(((ks * 2 + bkg) ^ fB) * 16);
            #pragma unroll
            for (int nip = 0; nip < 2; nip++) {
                const uint32_t baddr = cb + 16384 +
                    (uint32_t)((wn + nip * 16 + brow) * 64) + bchunk;
                uint32_t rh[4], rl[4];
                ldsm_x4(rh, baddr);
                ldsm_x4(rl, baddr + 8192);
                b_h[nip * 2 + 0][0] = rh[0]; b_h[nip * 2 + 0][1] = rh[1];
                b_h[nip * 2 + 1][0] = rh[2]; b_h[nip * 2 + 1][1] = rh[3];
                b_l[nip * 2 + 0][0] = rl[0]; b_l[nip * 2 + 0][1] = rl[1];
                b_l[nip * 2 + 1][0] = rl[2]; b_l[nip * 2 + 1][1] = rl[3];
            }
            #pragma unroll
            for (int mi = 0; mi < 4; mi++)
                #pragma unroll
                for (int ni = 0; ni < 4; ni++) {
                    mma_bf16(acc[mi][ni], a_l[mi], b_h[ni]);
                    mma_bf16(acc[mi][ni], a_h[mi], b_l[ni]);
                    mma_bf16(acc[mi][ni], a_h[mi], b_h[ni]);
                }
        }
        __syncthreads();
    }

    const float sc = *scale_ptr;
    const int g = lane >> 2, tg = lane & 3;
    #pragma unroll
    for (int mi = 0; mi < 4; mi++) {
        const int r0 = bm + wm + mi * 16 + g;
        #pragma unroll
        for (int ni = 0; ni < 4; ni++) {
            const int col = bn + wn + ni * 8 + tg * 2;
            *(float2*)(Cout + (size_t)r0 * V_ + col) =
                make_float2(acc[mi][ni][0] * sc, acc[mi][ni][1] * sc);
            *(float2*)(Cout + (size_t)(r0 + 8) * V_ + col) =
                make_float2(acc[mi][ni][2] * sc, acc[mi][ni][3] * sc);
        }
    }
}

// ---------------- launch ----------------
extern "C" void kernel_launch(void* const* d_in, const int* in_sizes, int n_in,
                              void* d_out, int out_size) {
    const float* x      = (const float*)d_in[0];
    const float* basis  = (const float*)d_in[1];
    const float* qc     = (const float*)d_in[2];
    const float* kc     = (const float*)d_in[3];
    const float* vc     = (const float*)d_in[4];
    const float* oc     = (const float*)d_in[5];
    const float* decay  = (const float*)d_in[6];
    const float* oscale = (const float*)d_in[7];
    float* out = (float*)d_out;

    cudaFuncSetAttribute(qkv_mma_kernel, cudaFuncAttributeMaxDynamicSharedMemorySize, 3 * QBUF);
    cudaFuncSetAttribute(out2_mma_kernel, cudaFuncAttributeMaxDynamicSharedMemorySize, 2 * QBUF);

    cvt_x_kernel<<<(MT * V_) / 1024, 256>>>(x);
    cvt_basis_kernel<<<(V_ * NB2) / 1024, 256>>>(basis);
    logits_kernel<<<dim3(3, 8), 256>>>(basis, qc, kc, vc);
    softmax_w_kernel<<<3 * C_, 256>>>();
    qkv_mma_kernel<<<dim3(3, MT / 128), 256, 3 * QBUF>>>();
    chunk_g_kernel<<<dim3(NCH, B_), 256>>>(decay);
    scan_kernel<<<128, 256>>>(decay);
    retr_kernel<<<dim3(NCH, B_), 256>>>(decay, oc);
    out2_mma_kernel<<<dim3(V_ / 128, MT / 128), 256, 2 * QBUF>>>(out, oscale);
}